// round 10
// baseline (speedup 1.0000x reference)
#include <cuda_runtime.h>
#include <cuda_bf16.h>
#include <cstdint>

// Problem constants
#define BB   32      // batch
#define DD   4096    // model dim
#define HH   32      // q heads
#define HKV  8       // kv heads
#define GG   4       // q heads per kv head
#define DH   128     // head dim
#define TT   4096    // cache length
#define EQKV 6144    // 4096 + 1024 + 1024
#define SPL  4       // K splits for mma projections
#define KSP  1024    // DD / SPL

// attention split config
#define TCH    512   // tokens per CTA
#define NSPLIT 8     // TT / TCH

// ---------------- scratch (device globals; no runtime allocation) ----------------
__device__ float g_v [BB * HKV * DH];
__device__ float g_q [BB * HH * DH];
__device__ float g_k [BB * HKV * DH];
__device__ float g_attn[BB * HH * DH];
__device__ uint32_t g_xhi[BB * DD / 2];   // packed bf16x2 hi of x
__device__ uint32_t g_xlo[BB * DD / 2];   // packed bf16x2 lo of x
__device__ uint32_t g_ahi[BB * DD / 2];   // packed bf16x2 hi of attn out
__device__ uint32_t g_alo[BB * DD / 2];
__device__ float g_P1[SPL * BB * EQKV];               // qkv partials
__device__ float g_P2[SPL * BB * DD];                 // wo partials
__device__ float g_pacc[BB * HKV * NSPLIT * GG * DH]; // flash partial acc
__device__ float g_pml [BB * HKV * NSPLIT * GG * 2];  // flash partial (m,l)

// ---------------- bf16 mma helper ----------------
__device__ __forceinline__ void mma_bf16(float* c, const uint32_t* a, uint32_t b0, uint32_t b1)
{
    asm volatile(
        "mma.sync.aligned.m16n8k16.row.col.f32.bf16.bf16.f32 "
        "{%0,%1,%2,%3}, {%4,%5,%6,%7}, {%8,%9}, {%0,%1,%2,%3};"
        : "+f"(c[0]), "+f"(c[1]), "+f"(c[2]), "+f"(c[3])
        : "r"(a[0]), "r"(a[1]), "r"(a[2]), "r"(a[3]), "r"(b0), "r"(b1));
}

__device__ __forceinline__ uint32_t cvt_bf16x2(float hi_elem, float lo_elem)
{
    // result: upper 16 = bf16(hi_elem), lower 16 = bf16(lo_elem)
    uint32_t r;
    asm("cvt.rn.bf16x2.f32 %0, %1, %2;" : "=r"(r) : "f"(hi_elem), "f"(lo_elem));
    return r;
}

// ---------------- fp32 -> packed bf16 hi/lo conversion ----------------
// hi = truncate-to-bf16 (exact, top 16 bits); lo = rn-bf16(x - hi). 2 elements/thread.
__global__ void conv_hilo_kernel(const float* __restrict__ src,
                                 uint32_t* __restrict__ hi, uint32_t* __restrict__ lo,
                                 int npairs)
{
    int i = blockIdx.x * 256 + threadIdx.x;
    if (i >= npairs) return;
    float2 v = ((const float2*)src)[i];
    uint32_t u0 = __float_as_uint(v.x), u1 = __float_as_uint(v.y);
    hi[i] = __byte_perm(u0, u1, 0x7632);          // {bf16(v.y)|bf16(v.x)} truncated
    float l0 = v.x - __uint_as_float(u0 & 0xFFFF0000u);
    float l1 = v.y - __uint_as_float(u1 & 0xFFFF0000u);
    lo[i] = cvt_bf16x2(l1, l0);
}

// ---------------- tensor-core projection ----------------
// out[b][e] = sum_d x[b][d] * w[d][e], bf16x3 split, m16n8k16 mma.
// CTA: 128 threads = 4 warps; warp owns 32 cols (4 n8 blocks); CTA N-tile = 128.
// K-split over blockIdx.y (KSP rows each).
__device__ __forceinline__ void proj_mma_body(
    const uint32_t* __restrict__ xhi, const uint32_t* __restrict__ xlo,
    const float* __restrict__ w, int Ew, int le0, int gcol0,
    float* __restrict__ part, int partE)
{
    const int tid = threadIdx.x;
    const int wid = tid >> 5, lane = tid & 31;
    const int g = lane >> 2, tig = lane & 3;
    const int nwarp0 = wid * 32;            // warp's first col within CTA tile
    const int k0base = blockIdx.y * KSP;

    float acc[4][2][4];                     // [n8 block][m tile][c0..c3]
    #pragma unroll
    for (int nb = 0; nb < 4; nb++)
        #pragma unroll
        for (int mt = 0; mt < 2; mt++)
            #pragma unroll
            for (int r = 0; r < 4; r++) acc[nb][mt][r] = 0.f;

    for (int c = 0; c < KSP / 16; c++) {
        const int k0 = k0base + c * 16;

        // ---- A fragments (packed bf16x2 pairs, direct gmem/L1) ----
        uint32_t ahi[2][4], alo[2][4];
        #pragma unroll
        for (int mt = 0; mt < 2; mt++) {
            size_t base = (size_t)(mt * 16 + g) * (DD / 2) + (k0 >> 1) + tig;
            ahi[mt][0] = xhi[base];
            ahi[mt][1] = xhi[base + 8 * (DD / 2)];
            ahi[mt][2] = xhi[base + 4];
            ahi[mt][3] = xhi[base + 8 * (DD / 2) + 4];
            alo[mt][0] = xlo[base];
            alo[mt][1] = xlo[base + 8 * (DD / 2)];
            alo[mt][2] = xlo[base + 4];
            alo[mt][3] = xlo[base + 8 * (DD / 2) + 4];
        }

        // ---- B fp32 loads, all 4 n8 blocks hoisted (MLP) ----
        const float* wk0 = w + (size_t)(k0 + 2 * tig) * Ew + le0 + nwarp0 + g;
        float bf[4][4];
        #pragma unroll
        for (int nb = 0; nb < 4; nb++) {
            const float* wp = wk0 + nb * 8;
            bf[nb][0] = wp[0];
            bf[nb][1] = wp[Ew];
            bf[nb][2] = wp[(size_t)8 * Ew];
            bf[nb][3] = wp[(size_t)9 * Ew];
        }

        // ---- convert + mma ----
        #pragma unroll
        for (int nb = 0; nb < 4; nb++) {
            uint32_t u0 = __float_as_uint(bf[nb][0]), u1 = __float_as_uint(bf[nb][1]);
            uint32_t u2 = __float_as_uint(bf[nb][2]), u3 = __float_as_uint(bf[nb][3]);
            uint32_t bhi0 = __byte_perm(u0, u1, 0x7632);
            uint32_t bhi1 = __byte_perm(u2, u3, 0x7632);
            float l0 = bf[nb][0] - __uint_as_float(u0 & 0xFFFF0000u);
            float l1 = bf[nb][1] - __uint_as_float(u1 & 0xFFFF0000u);
            float l2 = bf[nb][2] - __uint_as_float(u2 & 0xFFFF0000u);
            float l3 = bf[nb][3] - __uint_as_float(u3 & 0xFFFF0000u);
            uint32_t blo0 = cvt_bf16x2(l1, l0);
            uint32_t blo1 = cvt_bf16x2(l3, l2);
            #pragma unroll
            for (int mt = 0; mt < 2; mt++) {
                mma_bf16(acc[nb][mt], ahi[mt], bhi0, bhi1);   // hi*hi
                mma_bf16(acc[nb][mt], ahi[mt], blo0, blo1);   // hi*lo
                mma_bf16(acc[nb][mt], alo[mt], bhi0, bhi1);   // lo*hi
            }
        }
    }

    // ---- writeback partials ----
    float* pb = part + (size_t)blockIdx.y * BB * partE;
    #pragma unroll
    for (int nb = 0; nb < 4; nb++) {
        int ecol = gcol0 + nwarp0 + nb * 8 + 2 * tig;
        #pragma unroll
        for (int mt = 0; mt < 2; mt++) {
            int brow = mt * 16 + g;
            *(float2*)(pb + (size_t)brow * partE + ecol) =
                make_float2(acc[nb][mt][0], acc[nb][mt][1]);
            *(float2*)(pb + (size_t)(brow + 8) * partE + ecol) =
                make_float2(acc[nb][mt][2], acc[nb][mt][3]);
        }
    }
}

__global__ void __launch_bounds__(128)
proj_qkv_mma(const float* __restrict__ wq, const float* __restrict__ wk,
             const float* __restrict__ wv)
{
    int e0 = blockIdx.x * 128;
    const float* w; int Ew, le0;
    if (e0 < 4096)      { w = wq; Ew = 4096; le0 = e0; }
    else if (e0 < 5120) { w = wk; Ew = 1024; le0 = e0 - 4096; }
    else                { w = wv; Ew = 1024; le0 = e0 - 5120; }
    proj_mma_body(g_xhi, g_xlo, w, Ew, le0, e0, g_P1, EQKV);
}

__global__ void __launch_bounds__(128)
proj_o_mma(const float* __restrict__ wo)
{
    int e0 = blockIdx.x * 128;
    proj_mma_body(g_ahi, g_alo, wo, DD, e0, e0, g_P2, DD);
}

// ---------------- fused split-reduce + RoPE ----------------
// grid (48, BB), block 128.  hh<32: q head; 32..39: k head; 40..47: v head (no rotate).
__global__ void __launch_bounds__(128)
fused_reduce_rot_kernel(const float* __restrict__ rot, int rot_b_stride)
{
    const int hh = blockIdx.x, b = blockIdx.y, tid = threadIdx.x;
    int col;
    if (hh < 32)      col = hh * 128 + tid;
    else if (hh < 40) col = 4096 + (hh - 32) * 128 + tid;
    else              col = 5120 + (hh - 40) * 128 + tid;

    const float* p = g_P1 + (size_t)b * EQKV + col;
    float s = 0.f;
    #pragma unroll
    for (int sp = 0; sp < SPL; sp++)
        s += p[(size_t)sp * BB * EQKV];

    if (hh >= 40) {                      // v: plain reduce
        g_v[(size_t)b * 1024 + (hh - 40) * 128 + tid] = s;
        return;
    }

    __shared__ float xsr[DH];
    xsr[tid] = s;
    __syncthreads();
    const float* R = rot + (size_t)b * rot_b_stride;
    float a = 0.f;
    #pragma unroll 8
    for (int dd = 0; dd < DH; dd++) a += xsr[dd] * R[dd * DH + tid];

    if (hh < 32) g_q[(size_t)(b * HH + hh) * DH + tid] = a;
    else         g_k[(size_t)(b * HKV + (hh - 32)) * DH + tid] = a;
}

// ---------------- reduce wo partials ----------------
__global__ void reduce_o_kernel(float* __restrict__ out)
{
    int idx = blockIdx.x * 256 + threadIdx.x;
    if (idx >= BB * DD) return;
    int b = idx >> 12, col = idx & 4095;
    float s = 0.f;
    #pragma unroll
    for (int sp = 0; sp < SPL; sp++)
        s += g_P2[((size_t)sp * BB + b) * DD + col];
    out[b * DD + col] = s;
}

// ---------------- flash decode: direct-LDG, 512 tokens/CTA, single-pass softmax ----------------
// grid (NSPLIT, HKV, BB), block 256 (8 warps x 64 tokens).
__global__ void __launch_bounds__(256, 3)
attn_kernel(const float* __restrict__ kc, const float* __restrict__ vc,
            const int* __restrict__ sp_ptr)
{
    __shared__ float s_q  [GG * DH];
    __shared__ float s_sc [TCH * GG];
    __shared__ float s_wm [8 * GG];
    __shared__ float s_sl [8 * GG];
    __shared__ float s_MM [GG];
    __shared__ float s_out[8 * GG * DH];

    const int chunk = blockIdx.x, kvh = blockIdx.y, b = blockIdx.z;
    const int sp = *sp_ptr;
    const int t0 = chunk * TCH;
    if (t0 > sp) return;

    const int tid = threadIdx.x;
    const int wid = tid >> 5, lane = tid & 31;
    const int bkv = b * HKV + kvh;

    const float* kbase = kc + (size_t)bkv * TT * DH;
    const float* vbase = vc + (size_t)bkv * TT * DH;
    const float* gk = g_k + (size_t)bkv * DH;
    const float* gv = g_v + (size_t)bkv * DH;

    if (tid < 128) {
        int g = tid >> 5, c = tid & 31;
        const float sc = 0.08838834764831845f;   // 1/sqrt(128)
        float4 qv = *(const float4*)(g_q + (size_t)(b * HH + kvh * GG + g) * DH + c * 4);
        ((float4*)s_q)[g * 32 + c] = make_float4(qv.x * sc, qv.y * sc, qv.z * sc, qv.w * sc);
    }
    __syncthreads();

    const int tokg = lane >> 4, dg = lane & 15;
    const int jb = wid * 64;

    float4 qr0[GG], qr1[GG];
    #pragma unroll
    for (int g = 0; g < GG; g++) {
        qr0[g] = *(const float4*)(s_q + g * DH + dg * 4);
        qr1[g] = *(const float4*)(s_q + g * DH + dg * 4 + 64);
    }

    float wm0 = -1e30f, wm1 = -1e30f, wm2 = -1e30f, wm3 = -1e30f;
    float4 ka, kb;
    {
        int t = t0 + jb + tokg;
        const float* kp = (t == sp) ? gk : (kbase + (size_t)t * DH);
        ka = *(const float4*)(kp + dg * 4);
        kb = *(const float4*)(kp + dg * 4 + 64);
    }
    #pragma unroll 8
    for (int it = 0; it < 32; it++) {
        int jl = jb + it * 2 + tokg;
        int t = t0 + jl;
        float4 ca = ka, cb = kb;
        if (it < 31) {
            int tn = t0 + jb + (it + 1) * 2 + tokg;
            const float* kp = (tn == sp) ? gk : (kbase + (size_t)tn * DH);
            ka = *(const float4*)(kp + dg * 4);
            kb = *(const float4*)(kp + dg * 4 + 64);
        }
        float s0 = ca.x*qr0[0].x + ca.y*qr0[0].y + ca.z*qr0[0].z + ca.w*qr0[0].w
                 + cb.x*qr1[0].x + cb.y*qr1[0].y + cb.z*qr1[0].z + cb.w*qr1[0].w;
        float s1 = ca.x*qr0[1].x + ca.y*qr0[1].y + ca.z*qr0[1].z + ca.w*qr0[1].w
                 + cb.x*qr1[1].x + cb.y*qr1[1].y + cb.z*qr1[1].z + cb.w*qr1[1].w;
        float s2 = ca.x*qr0[2].x + ca.y*qr0[2].y + ca.z*qr0[2].z + ca.w*qr0[2].w
                 + cb.x*qr1[2].x + cb.y*qr1[2].y + cb.z*qr1[2].z + cb.w*qr1[2].w;
        float s3 = ca.x*qr0[3].x + ca.y*qr0[3].y + ca.z*qr0[3].z + ca.w*qr0[3].w
                 + cb.x*qr1[3].x + cb.y*qr1[3].y + cb.z*qr1[3].z + cb.w*qr1[3].w;
        #pragma unroll
        for (int off = 1; off <= 8; off <<= 1) {
            s0 += __shfl_xor_sync(0xffffffffu, s0, off);
            s1 += __shfl_xor_sync(0xffffffffu, s1, off);
            s2 += __shfl_xor_sync(0xffffffffu, s2, off);
            s3 += __shfl_xor_sync(0xffffffffu, s3, off);
        }
        if (t > sp) { s0 = s1 = s2 = s3 = -1e30f; }
        if (dg == 0)
            ((float4*)s_sc)[jl] = make_float4(s0, s1, s2, s3);
        wm0 = fmaxf(wm0, s0); wm1 = fmaxf(wm1, s1);
        wm2 = fmaxf(wm2, s2); wm3 = fmaxf(wm3, s3);
    }
    wm0 = fmaxf(wm0, __shfl_xor_sync(0xffffffffu, wm0, 16));
    wm1 = fmaxf(wm1, __shfl_xor_sync(0xffffffffu, wm1, 16));
    wm2 = fmaxf(wm2, __shfl_xor_sync(0xffffffffu, wm2, 16));
    wm3 = fmaxf(wm3, __shfl_xor_sync(0xffffffffu, wm3, 16));
    if (lane == 0) {
        s_wm[wid * 4 + 0] = wm0; s_wm[wid * 4 + 1] = wm1;
        s_wm[wid * 4 + 2] = wm2; s_wm[wid * 4 + 3] = wm3;
    }
    __syncthreads();

    if (tid < 4) {
        float m = s_wm[tid];
        #pragma unroll
        for (int w = 1; w < 8; w++) m = fmaxf(m, s_wm[w * 4 + tid]);
        s_MM[tid] = m;
    }
    __syncthreads();

    {
        float4 sva = ((float4*)s_sc)[tid];
        float4 svb = ((float4*)s_sc)[tid + 256];
        float m0 = s_MM[0], m1 = s_MM[1], m2 = s_MM[2], m3 = s_MM[3];
        float pa0 = __expf(sva.x - m0), pb0 = __expf(svb.x - m0);
        float pa1 = __expf(sva.y - m1), pb1 = __expf(svb.y - m1);
        float pa2 = __expf(sva.z - m2), pb2 = __expf(svb.z - m2);
        float pa3 = __expf(sva.w - m3), pb3 = __expf(svb.w - m3);
        ((float4*)s_sc)[tid]       = make_float4(pa0, pa1, pa2, pa3);
        ((float4*)s_sc)[tid + 256] = make_float4(pb0, pb1, pb2, pb3);
        float p0 = pa0 + pb0, p1 = pa1 + pb1, p2 = pa2 + pb2, p3 = pa3 + pb3;
        #pragma unroll
        for (int off = 1; off <= 16; off <<= 1) {
            p0 += __shfl_xor_sync(0xffffffffu, p0, off);
            p1 += __shfl_xor_sync(0xffffffffu, p1, off);
            p2 += __shfl_xor_sync(0xffffffffu, p2, off);
            p3 += __shfl_xor_sync(0xffffffffu, p3, off);
        }
        if (lane == 0) {
            s_sl[wid * 4 + 0] = p0; s_sl[wid * 4 + 1] = p1;
            s_sl[wid * 4 + 2] = p2; s_sl[wid * 4 + 3] = p3;
        }
    }
    __syncthreads();

    if (tid < 4) {
        float L = 0.f;
        #pragma unroll
        for (int w = 0; w < 8; w++) L += s_sl[w * 4 + tid];
        size_t mlb = (((size_t)bkv * NSPLIT + chunk) * GG + tid) * 2;
        g_pml[mlb] = s_MM[tid];
        g_pml[mlb + 1] = L;
    }

    float4 a0 = {0,0,0,0}, a1 = {0,0,0,0}, a2 = {0,0,0,0}, a3 = {0,0,0,0};
    #pragma unroll 4
    for (int jo = 0; jo < 64; jo += 4) {
        float4 vv[4], p4[4];
        #pragma unroll
        for (int u = 0; u < 4; u++) {
            int t = t0 + jb + jo + u;
            const float* vp = (t == sp) ? gv : (vbase + (size_t)t * DH);
            vv[u] = *(const float4*)(vp + lane * 4);
            p4[u] = ((float4*)s_sc)[jb + jo + u];
        }
        #pragma unroll
        for (int u = 0; u < 4; u++) {
            a0.x += p4[u].x*vv[u].x; a0.y += p4[u].x*vv[u].y; a0.z += p4[u].x*vv[u].z; a0.w += p4[u].x*vv[u].w;
            a1.x += p4[u].y*vv[u].x; a1.y += p4[u].y*vv[u].y; a1.z += p4[u].y*vv[u].z; a1.w += p4[u].y*vv[u].w;
            a2.x += p4[u].z*vv[u].x; a2.y += p4[u].z*vv[u].y; a2.z += p4[u].z*vv[u].z; a2.w += p4[u].z*vv[u].w;
            a3.x += p4[u].w*vv[u].x; a3.y += p4[u].w*vv[u].y; a3.z += p4[u].w*vv[u].z; a3.w += p4[u].w*vv[u].w;
        }
    }
    {
        float* ob = s_out + wid * (GG * DH);
        *(float4*)(ob + 0 * DH + lane * 4) = a0;
        *(float4*)(ob + 1 * DH + lane * 4) = a1;
        *(float4*)(ob + 2 * DH + lane * 4) = a2;
        *(float4*)(ob + 3 * DH + lane * 4) = a3;
    }
    __syncthreads();

    size_t obase = (((size_t)bkv * NSPLIT + chunk) * GG) * DH;
    #pragma unroll
    for (int r = tid; r < GG * DH; r += 256) {
        float s = 0.f;
        #pragma unroll
        for (int w = 0; w < 8; w++) s += s_out[w * (GG * DH) + r];
        g_pacc[obase + r] = s;
    }
}

// ---------------- combine split-KV partials ----------------
__global__ void combine_kernel(const int* __restrict__ sp_ptr)
{
    const int h = blockIdx.x, b = blockIdx.y, d = threadIdx.x;
    const int sp = *sp_ptr;
    const int nact = sp / TCH + 1;
    const int kvh = h >> 2, g = h & 3;
    const int bkv = b * HKV + kvh;

    float M = -1e30f;
    for (int c = 0; c < nact; c++)
        M = fmaxf(M, g_pml[(((size_t)bkv * NSPLIT + c) * GG + g) * 2]);

    float L = 0.f, acc = 0.f;
    for (int c = 0; c < nact; c++) {
        size_t mlb = (((size_t)bkv * NSPLIT + c) * GG + g) * 2;
        float f = __expf(g_pml[mlb] - M);
        L += g_pml[mlb + 1] * f;
        acc += g_pacc[(((size_t)bkv * NSPLIT + c) * GG + g) * DH + d] * f;
    }
    g_attn[(size_t)(b * HH + h) * DH + d] = acc / L;
}

// ---------------- launcher ----------------
extern "C" void kernel_launch(void* const* d_in, const int* in_sizes, int n_in,
                              void* d_out, int out_size)
{
    const float* x   = (const float*)d_in[0];
    const float* wq  = (const float*)d_in[1];
    const float* wk  = (const float*)d_in[2];
    const float* wv  = (const float*)d_in[3];
    const float* wo  = (const float*)d_in[4];
    const float* rot = (const float*)d_in[5];
    // d_in[6] = attn_mask: not read (semantics derived from start_pos)
    const float* kc  = (const float*)d_in[7];
    const float* vc  = (const float*)d_in[8];
    const int*   sp  = (const int*)d_in[9];
    float* out = (float*)d_out;

    int rot_b_stride = (in_sizes[5] >= BB * DH * DH) ? DH * DH : 0;

    uint32_t *xhi_p, *xlo_p, *ahi_p, *alo_p;
    float* attn_p;
    cudaGetSymbolAddress((void**)&xhi_p, g_xhi);
    cudaGetSymbolAddress((void**)&xlo_p, g_xlo);
    cudaGetSymbolAddress((void**)&ahi_p, g_ahi);
    cudaGetSymbolAddress((void**)&alo_p, g_alo);
    cudaGetSymbolAddress((void**)&attn_p, g_attn);

    const int NPAIRS = BB * DD / 2;   // 65536

    conv_hilo_kernel<<<(NPAIRS + 255) / 256, 256>>>(x, xhi_p, xlo_p, NPAIRS);
    proj_qkv_mma<<<dim3(EQKV / 128, SPL), 128>>>(wq, wk, wv);
    fused_reduce_rot_kernel<<<dim3(48, BB), 128>>>(rot, rot_b_stride);
    attn_kernel<<<dim3(NSPLIT, HKV, BB), 256>>>(kc, vc, sp);
    combine_kernel<<<dim3(HH, BB), DH>>>(sp);
    conv_hilo_kernel<<<(NPAIRS + 255) / 256, 256>>>(attn_p, ahi_p, alo_p, NPAIRS);
    proj_o_mma<<<dim3(DD / 128, SPL), 128>>>(wo);
    reduce_o_kernel<<<(BB * DD + 255) / 256, 256>>>(out);
}

// round 11
// speedup vs baseline: 1.5282x; 1.5282x over previous
#include <cuda_runtime.h>
#include <cuda_bf16.h>
#include <cstdint>

// Problem constants
#define BB   32      // batch
#define DD   4096    // model dim
#define HH   32      // q heads
#define HKV  8       // kv heads
#define GG   4       // q heads per kv head
#define DH   128     // head dim
#define TT   4096    // cache length
#define EQKV 6144    // 4096 + 1024 + 1024
#define SPL  16      // K splits for mma projections
#define KSP  256     // DD / SPL

// attention split config
#define TCH    512   // tokens per CTA
#define NSPLIT 8     // TT / TCH

// ---------------- scratch (device globals; no runtime allocation) ----------------
__device__ float g_v [BB * HKV * DH];
__device__ float g_q [BB * HH * DH];
__device__ float g_k [BB * HKV * DH];
__device__ float g_attn[BB * HH * DH];
__device__ uint32_t g_xhi[BB * DD / 2];   // packed bf16x2 hi of x
__device__ uint32_t g_xlo[BB * DD / 2];   // packed bf16x2 lo of x
__device__ uint32_t g_ahi[BB * DD / 2];   // packed bf16x2 hi of attn out
__device__ uint32_t g_alo[BB * DD / 2];
__device__ float g_P1[SPL * BB * EQKV];               // qkv partials
__device__ float g_P2[SPL * BB * DD];                 // wo partials
__device__ float g_pacc[BB * HKV * NSPLIT * GG * DH]; // flash partial acc
__device__ float g_pml [BB * HKV * NSPLIT * GG * 2];  // flash partial (m,l)

// ---------------- bf16 mma helper ----------------
__device__ __forceinline__ void mma_bf16(float* c, const uint32_t* a, uint32_t b0, uint32_t b1)
{
    asm volatile(
        "mma.sync.aligned.m16n8k16.row.col.f32.bf16.bf16.f32 "
        "{%0,%1,%2,%3}, {%4,%5,%6,%7}, {%8,%9}, {%0,%1,%2,%3};"
        : "+f"(c[0]), "+f"(c[1]), "+f"(c[2]), "+f"(c[3])
        : "r"(a[0]), "r"(a[1]), "r"(a[2]), "r"(a[3]), "r"(b0), "r"(b1));
}

__device__ __forceinline__ uint32_t cvt_bf16x2(float hi_elem, float lo_elem)
{
    uint32_t r;
    asm("cvt.rn.bf16x2.f32 %0, %1, %2;" : "=r"(r) : "f"(hi_elem), "f"(lo_elem));
    return r;
}

// ---------------- fp32 -> packed bf16 hi/lo conversion ----------------
// hi = truncate-to-bf16 (exact, top 16 bits); lo = rn-bf16(x - hi). 2 elements/thread.
__global__ void conv_hilo_kernel(const float* __restrict__ src,
                                 uint32_t* __restrict__ hi, uint32_t* __restrict__ lo,
                                 int npairs)
{
    int i = blockIdx.x * 256 + threadIdx.x;
    if (i >= npairs) return;
    float2 v = ((const float2*)src)[i];
    uint32_t u0 = __float_as_uint(v.x), u1 = __float_as_uint(v.y);
    hi[i] = __byte_perm(u0, u1, 0x7632);          // {bf16(v.y)|bf16(v.x)} truncated
    float l0 = v.x - __uint_as_float(u0 & 0xFFFF0000u);
    float l1 = v.y - __uint_as_float(u1 & 0xFFFF0000u);
    lo[i] = cvt_bf16x2(l1, l0);
}

// ---------------- tensor-core projection ----------------
// out[b][e] = sum_d x[b][d] * w[d][e], bf16x3 split, m16n8k16 mma.
// CTA: 128 threads = 4 warps; warp owns 32 cols (4 n8 blocks); CTA N-tile = 128.
// K-split over blockIdx.y (KSP rows each).
__device__ __forceinline__ void proj_mma_body(
    const uint32_t* __restrict__ xhi, const uint32_t* __restrict__ xlo,
    const float* __restrict__ w, int Ew, int le0, int gcol0,
    float* __restrict__ part, int partE)
{
    const int tid = threadIdx.x;
    const int wid = tid >> 5, lane = tid & 31;
    const int g = lane >> 2, tig = lane & 3;
    const int nwarp0 = wid * 32;            // warp's first col within CTA tile
    const int k0base = blockIdx.y * KSP;

    float acc[4][2][4];                     // [n8 block][m tile][c0..c3]
    #pragma unroll
    for (int nb = 0; nb < 4; nb++)
        #pragma unroll
        for (int mt = 0; mt < 2; mt++)
            #pragma unroll
            for (int r = 0; r < 4; r++) acc[nb][mt][r] = 0.f;

    for (int c = 0; c < KSP / 16; c++) {
        const int k0 = k0base + c * 16;

        // ---- A fragments (packed bf16x2 pairs, direct gmem/L1) ----
        uint32_t ahi[2][4], alo[2][4];
        #pragma unroll
        for (int mt = 0; mt < 2; mt++) {
            size_t base = (size_t)(mt * 16 + g) * (DD / 2) + (k0 >> 1) + tig;
            ahi[mt][0] = xhi[base];
            ahi[mt][1] = xhi[base + 8 * (DD / 2)];
            ahi[mt][2] = xhi[base + 4];
            ahi[mt][3] = xhi[base + 8 * (DD / 2) + 4];
            alo[mt][0] = xlo[base];
            alo[mt][1] = xlo[base + 8 * (DD / 2)];
            alo[mt][2] = xlo[base + 4];
            alo[mt][3] = xlo[base + 8 * (DD / 2) + 4];
        }

        // ---- B fp32 loads, all 4 n8 blocks hoisted (MLP) ----
        const float* wk0 = w + (size_t)(k0 + 2 * tig) * Ew + le0 + nwarp0 + g;
        float bf[4][4];
        #pragma unroll
        for (int nb = 0; nb < 4; nb++) {
            const float* wp = wk0 + nb * 8;
            bf[nb][0] = wp[0];
            bf[nb][1] = wp[Ew];
            bf[nb][2] = wp[(size_t)8 * Ew];
            bf[nb][3] = wp[(size_t)9 * Ew];
        }

        // ---- convert + mma ----
        #pragma unroll
        for (int nb = 0; nb < 4; nb++) {
            uint32_t u0 = __float_as_uint(bf[nb][0]), u1 = __float_as_uint(bf[nb][1]);
            uint32_t u2 = __float_as_uint(bf[nb][2]), u3 = __float_as_uint(bf[nb][3]);
            uint32_t bhi0 = __byte_perm(u0, u1, 0x7632);
            uint32_t bhi1 = __byte_perm(u2, u3, 0x7632);
            float l0 = bf[nb][0] - __uint_as_float(u0 & 0xFFFF0000u);
            float l1 = bf[nb][1] - __uint_as_float(u1 & 0xFFFF0000u);
            float l2 = bf[nb][2] - __uint_as_float(u2 & 0xFFFF0000u);
            float l3 = bf[nb][3] - __uint_as_float(u3 & 0xFFFF0000u);
            uint32_t blo0 = cvt_bf16x2(l1, l0);
            uint32_t blo1 = cvt_bf16x2(l3, l2);
            #pragma unroll
            for (int mt = 0; mt < 2; mt++) {
                mma_bf16(acc[nb][mt], ahi[mt], bhi0, bhi1);   // hi*hi
                mma_bf16(acc[nb][mt], ahi[mt], blo0, blo1);   // hi*lo
                mma_bf16(acc[nb][mt], alo[mt], bhi0, bhi1);   // lo*hi
            }
        }
    }

    // ---- writeback partials ----
    float* pb = part + (size_t)blockIdx.y * BB * partE;
    #pragma unroll
    for (int nb = 0; nb < 4; nb++) {
        int ecol = gcol0 + nwarp0 + nb * 8 + 2 * tig;
        #pragma unroll
        for (int mt = 0; mt < 2; mt++) {
            int brow = mt * 16 + g;
            *(float2*)(pb + (size_t)brow * partE + ecol) =
                make_float2(acc[nb][mt][0], acc[nb][mt][1]);
            *(float2*)(pb + (size_t)(brow + 8) * partE + ecol) =
                make_float2(acc[nb][mt][2], acc[nb][mt][3]);
        }
    }
}

__global__ void __launch_bounds__(128)
proj_qkv_mma(const float* __restrict__ wq, const float* __restrict__ wk,
             const float* __restrict__ wv)
{
    int e0 = blockIdx.x * 128;
    const float* w; int Ew, le0;
    if (e0 < 4096)      { w = wq; Ew = 4096; le0 = e0; }
    else if (e0 < 5120) { w = wk; Ew = 1024; le0 = e0 - 4096; }
    else                { w = wv; Ew = 1024; le0 = e0 - 5120; }
    proj_mma_body(g_xhi, g_xlo, w, Ew, le0, e0, g_P1, EQKV);
}

__global__ void __launch_bounds__(128)
proj_o_mma(const float* __restrict__ wo)
{
    int e0 = blockIdx.x * 128;
    proj_mma_body(g_ahi, g_alo, wo, DD, e0, e0, g_P2, DD);
}

// ---------------- fused split-reduce + RoPE ----------------
// grid (48, BB), block 128.  hh<32: q head; 32..39: k head; 40..47: v head (no rotate).
__global__ void __launch_bounds__(128)
fused_reduce_rot_kernel(const float* __restrict__ rot, int rot_b_stride)
{
    const int hh = blockIdx.x, b = blockIdx.y, tid = threadIdx.x;
    int col;
    if (hh < 32)      col = hh * 128 + tid;
    else if (hh < 40) col = 4096 + (hh - 32) * 128 + tid;
    else              col = 5120 + (hh - 40) * 128 + tid;

    const float* p = g_P1 + (size_t)b * EQKV + col;
    float s = 0.f;
    #pragma unroll
    for (int sp = 0; sp < SPL; sp++)
        s += p[(size_t)sp * BB * EQKV];

    if (hh >= 40) {                      // v: plain reduce
        g_v[(size_t)b * 1024 + (hh - 40) * 128 + tid] = s;
        return;
    }

    __shared__ float xsr[DH];
    xsr[tid] = s;
    __syncthreads();
    const float* R = rot + (size_t)b * rot_b_stride;
    float a = 0.f;
    #pragma unroll 8
    for (int dd = 0; dd < DH; dd++) a += xsr[dd] * R[dd * DH + tid];

    if (hh < 32) g_q[(size_t)(b * HH + hh) * DH + tid] = a;
    else         g_k[(size_t)(b * HKV + (hh - 32)) * DH + tid] = a;
}

// ---------------- reduce wo partials ----------------
__global__ void reduce_o_kernel(float* __restrict__ out)
{
    int idx = blockIdx.x * 256 + threadIdx.x;
    if (idx >= BB * DD) return;
    int b = idx >> 12, col = idx & 4095;
    float s = 0.f;
    #pragma unroll
    for (int sp = 0; sp < SPL; sp++)
        s += g_P2[((size_t)sp * BB + b) * DD + col];
    out[b * DD + col] = s;
}

// ---------------- flash decode: direct-LDG, 512 tokens/CTA, single-pass softmax ----------------
// grid (NSPLIT, HKV, BB), block 256 (8 warps x 64 tokens).
__global__ void __launch_bounds__(256, 3)
attn_kernel(const float* __restrict__ kc, const float* __restrict__ vc,
            const int* __restrict__ sp_ptr)
{
    __shared__ float s_q  [GG * DH];
    __shared__ float s_sc [TCH * GG];
    __shared__ float s_wm [8 * GG];
    __shared__ float s_sl [8 * GG];
    __shared__ float s_MM [GG];
    __shared__ float s_out[8 * GG * DH];

    const int chunk = blockIdx.x, kvh = blockIdx.y, b = blockIdx.z;
    const int sp = *sp_ptr;
    const int t0 = chunk * TCH;
    if (t0 > sp) return;

    const int tid = threadIdx.x;
    const int wid = tid >> 5, lane = tid & 31;
    const int bkv = b * HKV + kvh;

    const float* kbase = kc + (size_t)bkv * TT * DH;
    const float* vbase = vc + (size_t)bkv * TT * DH;
    const float* gk = g_k + (size_t)bkv * DH;
    const float* gv = g_v + (size_t)bkv * DH;

    if (tid < 128) {
        int g = tid >> 5, c = tid & 31;
        const float sc = 0.08838834764831845f;   // 1/sqrt(128)
        float4 qv = *(const float4*)(g_q + (size_t)(b * HH + kvh * GG + g) * DH + c * 4);
        ((float4*)s_q)[g * 32 + c] = make_float4(qv.x * sc, qv.y * sc, qv.z * sc, qv.w * sc);
    }
    __syncthreads();

    const int tokg = lane >> 4, dg = lane & 15;
    const int jb = wid * 64;

    float4 qr0[GG], qr1[GG];
    #pragma unroll
    for (int g = 0; g < GG; g++) {
        qr0[g] = *(const float4*)(s_q + g * DH + dg * 4);
        qr1[g] = *(const float4*)(s_q + g * DH + dg * 4 + 64);
    }

    float wm0 = -1e30f, wm1 = -1e30f, wm2 = -1e30f, wm3 = -1e30f;
    float4 ka, kb;
    {
        int t = t0 + jb + tokg;
        const float* kp = (t == sp) ? gk : (kbase + (size_t)t * DH);
        ka = *(const float4*)(kp + dg * 4);
        kb = *(const float4*)(kp + dg * 4 + 64);
    }
    #pragma unroll 8
    for (int it = 0; it < 32; it++) {
        int jl = jb + it * 2 + tokg;
        int t = t0 + jl;
        float4 ca = ka, cb = kb;
        if (it < 31) {
            int tn = t0 + jb + (it + 1) * 2 + tokg;
            const float* kp = (tn == sp) ? gk : (kbase + (size_t)tn * DH);
            ka = *(const float4*)(kp + dg * 4);
            kb = *(const float4*)(kp + dg * 4 + 64);
        }
        float s0 = ca.x*qr0[0].x + ca.y*qr0[0].y + ca.z*qr0[0].z + ca.w*qr0[0].w
                 + cb.x*qr1[0].x + cb.y*qr1[0].y + cb.z*qr1[0].z + cb.w*qr1[0].w;
        float s1 = ca.x*qr0[1].x + ca.y*qr0[1].y + ca.z*qr0[1].z + ca.w*qr0[1].w
                 + cb.x*qr1[1].x + cb.y*qr1[1].y + cb.z*qr1[1].z + cb.w*qr1[1].w;
        float s2 = ca.x*qr0[2].x + ca.y*qr0[2].y + ca.z*qr0[2].z + ca.w*qr0[2].w
                 + cb.x*qr1[2].x + cb.y*qr1[2].y + cb.z*qr1[2].z + cb.w*qr1[2].w;
        float s3 = ca.x*qr0[3].x + ca.y*qr0[3].y + ca.z*qr0[3].z + ca.w*qr0[3].w
                 + cb.x*qr1[3].x + cb.y*qr1[3].y + cb.z*qr1[3].z + cb.w*qr1[3].w;
        #pragma unroll
        for (int off = 1; off <= 8; off <<= 1) {
            s0 += __shfl_xor_sync(0xffffffffu, s0, off);
            s1 += __shfl_xor_sync(0xffffffffu, s1, off);
            s2 += __shfl_xor_sync(0xffffffffu, s2, off);
            s3 += __shfl_xor_sync(0xffffffffu, s3, off);
        }
        if (t > sp) { s0 = s1 = s2 = s3 = -1e30f; }
        if (dg == 0)
            ((float4*)s_sc)[jl] = make_float4(s0, s1, s2, s3);
        wm0 = fmaxf(wm0, s0); wm1 = fmaxf(wm1, s1);
        wm2 = fmaxf(wm2, s2); wm3 = fmaxf(wm3, s3);
    }
    wm0 = fmaxf(wm0, __shfl_xor_sync(0xffffffffu, wm0, 16));
    wm1 = fmaxf(wm1, __shfl_xor_sync(0xffffffffu, wm1, 16));
    wm2 = fmaxf(wm2, __shfl_xor_sync(0xffffffffu, wm2, 16));
    wm3 = fmaxf(wm3, __shfl_xor_sync(0xffffffffu, wm3, 16));
    if (lane == 0) {
        s_wm[wid * 4 + 0] = wm0; s_wm[wid * 4 + 1] = wm1;
        s_wm[wid * 4 + 2] = wm2; s_wm[wid * 4 + 3] = wm3;
    }
    __syncthreads();

    if (tid < 4) {
        float m = s_wm[tid];
        #pragma unroll
        for (int w = 1; w < 8; w++) m = fmaxf(m, s_wm[w * 4 + tid]);
        s_MM[tid] = m;
    }
    __syncthreads();

    {
        float4 sva = ((float4*)s_sc)[tid];
        float4 svb = ((float4*)s_sc)[tid + 256];
        float m0 = s_MM[0], m1 = s_MM[1], m2 = s_MM[2], m3 = s_MM[3];
        float pa0 = __expf(sva.x - m0), pb0 = __expf(svb.x - m0);
        float pa1 = __expf(sva.y - m1), pb1 = __expf(svb.y - m1);
        float pa2 = __expf(sva.z - m2), pb2 = __expf(svb.z - m2);
        float pa3 = __expf(sva.w - m3), pb3 = __expf(svb.w - m3);
        ((float4*)s_sc)[tid]       = make_float4(pa0, pa1, pa2, pa3);
        ((float4*)s_sc)[tid + 256] = make_float4(pb0, pb1, pb2, pb3);
        float p0 = pa0 + pb0, p1 = pa1 + pb1, p2 = pa2 + pb2, p3 = pa3 + pb3;
        #pragma unroll
        for (int off = 1; off <= 16; off <<= 1) {
            p0 += __shfl_xor_sync(0xffffffffu, p0, off);
            p1 += __shfl_xor_sync(0xffffffffu, p1, off);
            p2 += __shfl_xor_sync(0xffffffffu, p2, off);
            p3 += __shfl_xor_sync(0xffffffffu, p3, off);
        }
        if (lane == 0) {
            s_sl[wid * 4 + 0] = p0; s_sl[wid * 4 + 1] = p1;
            s_sl[wid * 4 + 2] = p2; s_sl[wid * 4 + 3] = p3;
        }
    }
    __syncthreads();

    if (tid < 4) {
        float L = 0.f;
        #pragma unroll
        for (int w = 0; w < 8; w++) L += s_sl[w * 4 + tid];
        size_t mlb = (((size_t)bkv * NSPLIT + chunk) * GG + tid) * 2;
        g_pml[mlb] = s_MM[tid];
        g_pml[mlb + 1] = L;
    }

    float4 a0 = {0,0,0,0}, a1 = {0,0,0,0}, a2 = {0,0,0,0}, a3 = {0,0,0,0};
    #pragma unroll 4
    for (int jo = 0; jo < 64; jo += 4) {
        float4 vv[4], p4[4];
        #pragma unroll
        for (int u = 0; u < 4; u++) {
            int t = t0 + jb + jo + u;
            const float* vp = (t == sp) ? gv : (vbase + (size_t)t * DH);
            vv[u] = *(const float4*)(vp + lane * 4);
            p4[u] = ((float4*)s_sc)[jb + jo + u];
        }
        #pragma unroll
        for (int u = 0; u < 4; u++) {
            a0.x += p4[u].x*vv[u].x; a0.y += p4[u].x*vv[u].y; a0.z += p4[u].x*vv[u].z; a0.w += p4[u].x*vv[u].w;
            a1.x += p4[u].y*vv[u].x; a1.y += p4[u].y*vv[u].y; a1.z += p4[u].y*vv[u].z; a1.w += p4[u].y*vv[u].w;
            a2.x += p4[u].z*vv[u].x; a2.y += p4[u].z*vv[u].y; a2.z += p4[u].z*vv[u].z; a2.w += p4[u].z*vv[u].w;
            a3.x += p4[u].w*vv[u].x; a3.y += p4[u].w*vv[u].y; a3.z += p4[u].w*vv[u].z; a3.w += p4[u].w*vv[u].w;
        }
    }
    {
        float* ob = s_out + wid * (GG * DH);
        *(float4*)(ob + 0 * DH + lane * 4) = a0;
        *(float4*)(ob + 1 * DH + lane * 4) = a1;
        *(float4*)(ob + 2 * DH + lane * 4) = a2;
        *(float4*)(ob + 3 * DH + lane * 4) = a3;
    }
    __syncthreads();

    size_t obase = (((size_t)bkv * NSPLIT + chunk) * GG) * DH;
    #pragma unroll
    for (int r = tid; r < GG * DH; r += 256) {
        float s = 0.f;
        #pragma unroll
        for (int w = 0; w < 8; w++) s += s_out[w * (GG * DH) + r];
        g_pacc[obase + r] = s;
    }
}

// ---------------- combine split-KV partials ----------------
__global__ void combine_kernel(const int* __restrict__ sp_ptr)
{
    const int h = blockIdx.x, b = blockIdx.y, d = threadIdx.x;
    const int sp = *sp_ptr;
    const int nact = sp / TCH + 1;
    const int kvh = h >> 2, g = h & 3;
    const int bkv = b * HKV + kvh;

    float M = -1e30f;
    for (int c = 0; c < nact; c++)
        M = fmaxf(M, g_pml[(((size_t)bkv * NSPLIT + c) * GG + g) * 2]);

    float L = 0.f, acc = 0.f;
    for (int c = 0; c < nact; c++) {
        size_t mlb = (((size_t)bkv * NSPLIT + c) * GG + g) * 2;
        float f = __expf(g_pml[mlb] - M);
        L += g_pml[mlb + 1] * f;
        acc += g_pacc[(((size_t)bkv * NSPLIT + c) * GG + g) * DH + d] * f;
    }
    g_attn[(size_t)(b * HH + h) * DH + d] = acc / L;
}

// ---------------- launcher ----------------
extern "C" void kernel_launch(void* const* d_in, const int* in_sizes, int n_in,
                              void* d_out, int out_size)
{
    const float* x   = (const float*)d_in[0];
    const float* wq  = (const float*)d_in[1];
    const float* wk  = (const float*)d_in[2];
    const float* wv  = (const float*)d_in[3];
    const float* wo  = (const float*)d_in[4];
    const float* rot = (const float*)d_in[5];
    // d_in[6] = attn_mask: not read (semantics derived from start_pos)
    const float* kc  = (const float*)d_in[7];
    const float* vc  = (const float*)d_in[8];
    const int*   sp  = (const int*)d_in[9];
    float* out = (float*)d_out;

    int rot_b_stride = (in_sizes[5] >= BB * DH * DH) ? DH * DH : 0;

    uint32_t *xhi_p, *xlo_p, *ahi_p, *alo_p;
    float* attn_p;
    cudaGetSymbolAddress((void**)&xhi_p, g_xhi);
    cudaGetSymbolAddress((void**)&xlo_p, g_xlo);
    cudaGetSymbolAddress((void**)&ahi_p, g_ahi);
    cudaGetSymbolAddress((void**)&alo_p, g_alo);
    cudaGetSymbolAddress((void**)&attn_p, g_attn);

    const int NPAIRS = BB * DD / 2;   // 65536

    conv_hilo_kernel<<<(NPAIRS + 255) / 256, 256>>>(x, xhi_p, xlo_p, NPAIRS);
    proj_qkv_mma<<<dim3(EQKV / 128, SPL), 128>>>(wq, wk, wv);
    fused_reduce_rot_kernel<<<dim3(48, BB), 128>>>(rot, rot_b_stride);
    attn_kernel<<<dim3(NSPLIT, HKV, BB), 256>>>(kc, vc, sp);
    combine_kernel<<<dim3(HH, BB), DH>>>(sp);
    conv_hilo_kernel<<<(NPAIRS + 255) / 256, 256>>>(attn_p, ahi_p, alo_p, NPAIRS);
    proj_o_mma<<<dim3(DD / 128, SPL), 128>>>(wo);
    reduce_o_kernel<<<(BB * DD + 255) / 256, 256>>>(out);
}

// round 12
// speedup vs baseline: 1.5847x; 1.0370x over previous
#include <cuda_runtime.h>
#include <cuda_bf16.h>
#include <cstdint>

// Problem constants
#define BB   32      // batch
#define DD   4096    // model dim
#define HH   32      // q heads
#define HKV  8       // kv heads
#define GG   4       // q heads per kv head
#define DH   128     // head dim
#define TT   4096    // cache length
#define EQKV 6144    // 4096 + 1024 + 1024
#define SPL  16      // K splits for mma projections
#define KSP  256     // DD / SPL

// attention split config
#define TCH    256   // tokens per CTA
#define NSPLIT 16    // TT / TCH

// ---------------- scratch (device globals; no runtime allocation) ----------------
__device__ float g_v [BB * HKV * DH];
__device__ float g_q [BB * HH * DH];
__device__ float g_k [BB * HKV * DH];
__device__ uint32_t g_xhi[BB * DD / 2];   // packed bf16x2 hi of x
__device__ uint32_t g_xlo[BB * DD / 2];   // packed bf16x2 lo of x
__device__ uint32_t g_ahi[BB * DD / 2];   // packed bf16x2 hi of attn out
__device__ uint32_t g_alo[BB * DD / 2];
__device__ float g_P1[SPL * BB * EQKV];               // qkv partials
__device__ float g_P2[SPL * BB * DD];                 // wo partials
__device__ float g_pacc[BB * HKV * NSPLIT * GG * DH]; // flash partial acc
__device__ float g_pml [BB * HKV * NSPLIT * GG * 2];  // flash partial (m,l)

// ---------------- bf16 mma helper ----------------
__device__ __forceinline__ void mma_bf16(float* c, const uint32_t* a, uint32_t b0, uint32_t b1)
{
    asm volatile(
        "mma.sync.aligned.m16n8k16.row.col.f32.bf16.bf16.f32 "
        "{%0,%1,%2,%3}, {%4,%5,%6,%7}, {%8,%9}, {%0,%1,%2,%3};"
        : "+f"(c[0]), "+f"(c[1]), "+f"(c[2]), "+f"(c[3])
        : "r"(a[0]), "r"(a[1]), "r"(a[2]), "r"(a[3]), "r"(b0), "r"(b1));
}

__device__ __forceinline__ uint32_t cvt_bf16x2(float hi_elem, float lo_elem)
{
    uint32_t r;
    asm("cvt.rn.bf16x2.f32 %0, %1, %2;" : "=r"(r) : "f"(hi_elem), "f"(lo_elem));
    return r;
}

// ---------------- fp32 -> packed bf16 hi/lo conversion (x input) ----------------
__global__ void conv_hilo_kernel(const float* __restrict__ src,
                                 uint32_t* __restrict__ hi, uint32_t* __restrict__ lo,
                                 int npairs)
{
    int i = blockIdx.x * 256 + threadIdx.x;
    if (i >= npairs) return;
    float2 v = ((const float2*)src)[i];
    uint32_t u0 = __float_as_uint(v.x), u1 = __float_as_uint(v.y);
    hi[i] = __byte_perm(u0, u1, 0x7632);          // {bf16(v.y)|bf16(v.x)} truncated
    float l0 = v.x - __uint_as_float(u0 & 0xFFFF0000u);
    float l1 = v.y - __uint_as_float(u1 & 0xFFFF0000u);
    lo[i] = cvt_bf16x2(l1, l0);
}

// ---------------- tensor-core projection (bf16x3, software-pipelined) ----------------
// CTA: 128 threads = 4 warps; warp owns 32 cols; CTA N-tile 128; K-split blockIdx.y.
struct Frag {
    uint32_t ahi[2][4];
    uint32_t alo[2][4];
    float    bf[4][4];
};

__device__ __forceinline__ void load_frag(
    Frag& f,
    const uint32_t* __restrict__ xhi, const uint32_t* __restrict__ xlo,
    const float* __restrict__ w, int Ew, int wcol0,
    int k0, int g, int tig)
{
    #pragma unroll
    for (int mt = 0; mt < 2; mt++) {
        size_t base = (size_t)(mt * 16 + g) * (DD / 2) + (k0 >> 1) + tig;
        f.ahi[mt][0] = xhi[base];
        f.ahi[mt][1] = xhi[base + 8 * (DD / 2)];
        f.ahi[mt][2] = xhi[base + 4];
        f.ahi[mt][3] = xhi[base + 8 * (DD / 2) + 4];
        f.alo[mt][0] = xlo[base];
        f.alo[mt][1] = xlo[base + 8 * (DD / 2)];
        f.alo[mt][2] = xlo[base + 4];
        f.alo[mt][3] = xlo[base + 8 * (DD / 2) + 4];
    }
    const float* wk0 = w + (size_t)(k0 + 2 * tig) * Ew + wcol0;
    #pragma unroll
    for (int nb = 0; nb < 4; nb++) {
        const float* wp = wk0 + nb * 8;
        f.bf[nb][0] = wp[0];
        f.bf[nb][1] = wp[Ew];
        f.bf[nb][2] = wp[(size_t)8 * Ew];
        f.bf[nb][3] = wp[(size_t)9 * Ew];
    }
}

__device__ __forceinline__ void mma_frag(float acc[4][2][4], const Frag& f)
{
    #pragma unroll
    for (int nb = 0; nb < 4; nb++) {
        uint32_t u0 = __float_as_uint(f.bf[nb][0]), u1 = __float_as_uint(f.bf[nb][1]);
        uint32_t u2 = __float_as_uint(f.bf[nb][2]), u3 = __float_as_uint(f.bf[nb][3]);
        uint32_t bhi0 = __byte_perm(u0, u1, 0x7632);
        uint32_t bhi1 = __byte_perm(u2, u3, 0x7632);
        float l0 = f.bf[nb][0] - __uint_as_float(u0 & 0xFFFF0000u);
        float l1 = f.bf[nb][1] - __uint_as_float(u1 & 0xFFFF0000u);
        float l2 = f.bf[nb][2] - __uint_as_float(u2 & 0xFFFF0000u);
        float l3 = f.bf[nb][3] - __uint_as_float(u3 & 0xFFFF0000u);
        uint32_t blo0 = cvt_bf16x2(l1, l0);
        uint32_t blo1 = cvt_bf16x2(l3, l2);
        #pragma unroll
        for (int mt = 0; mt < 2; mt++) {
            mma_bf16(acc[nb][mt], f.ahi[mt], bhi0, bhi1);   // hi*hi
            mma_bf16(acc[nb][mt], f.ahi[mt], blo0, blo1);   // hi*lo
            mma_bf16(acc[nb][mt], f.alo[mt], bhi0, bhi1);   // lo*hi
        }
    }
}

__device__ __forceinline__ void proj_mma_body(
    const uint32_t* __restrict__ xhi, const uint32_t* __restrict__ xlo,
    const float* __restrict__ w, int Ew, int le0, int gcol0,
    float* __restrict__ part, int partE)
{
    const int tid = threadIdx.x;
    const int wid = tid >> 5, lane = tid & 31;
    const int g = lane >> 2, tig = lane & 3;
    const int nwarp0 = wid * 32;
    const int k0base = blockIdx.y * KSP;
    const int wcol0 = le0 + nwarp0 + g;

    float acc[4][2][4];
    #pragma unroll
    for (int nb = 0; nb < 4; nb++)
        #pragma unroll
        for (int mt = 0; mt < 2; mt++)
            #pragma unroll
            for (int r = 0; r < 4; r++) acc[nb][mt][r] = 0.f;

    const int NCH = KSP / 16;   // 16 chunks

    Frag fA, fB;
    load_frag(fA, xhi, xlo, w, Ew, wcol0, k0base, g, tig);

    #pragma unroll 2
    for (int c = 0; c < NCH; c += 2) {
        load_frag(fB, xhi, xlo, w, Ew, wcol0, k0base + (c + 1) * 16, g, tig);
        mma_frag(acc, fA);
        if (c + 2 < NCH)
            load_frag(fA, xhi, xlo, w, Ew, wcol0, k0base + (c + 2) * 16, g, tig);
        mma_frag(acc, fB);
    }

    // ---- writeback partials ----
    float* pb = part + (size_t)blockIdx.y * BB * partE;
    #pragma unroll
    for (int nb = 0; nb < 4; nb++) {
        int ecol = gcol0 + nwarp0 + nb * 8 + 2 * tig;
        #pragma unroll
        for (int mt = 0; mt < 2; mt++) {
            int brow = mt * 16 + g;
            *(float2*)(pb + (size_t)brow * partE + ecol) =
                make_float2(acc[nb][mt][0], acc[nb][mt][1]);
            *(float2*)(pb + (size_t)(brow + 8) * partE + ecol) =
                make_float2(acc[nb][mt][2], acc[nb][mt][3]);
        }
    }
}

__global__ void __launch_bounds__(128)
proj_qkv_mma(const float* __restrict__ wq, const float* __restrict__ wk,
             const float* __restrict__ wv)
{
    int e0 = blockIdx.x * 128;
    const float* w; int Ew, le0;
    if (e0 < 4096)      { w = wq; Ew = 4096; le0 = e0; }
    else if (e0 < 5120) { w = wk; Ew = 1024; le0 = e0 - 4096; }
    else                { w = wv; Ew = 1024; le0 = e0 - 5120; }
    proj_mma_body(g_xhi, g_xlo, w, Ew, le0, e0, g_P1, EQKV);
}

__global__ void __launch_bounds__(128)
proj_o_mma(const float* __restrict__ wo)
{
    int e0 = blockIdx.x * 128;
    proj_mma_body(g_ahi, g_alo, wo, DD, e0, e0, g_P2, DD);
}

// ---------------- fused split-reduce + RoPE ----------------
// grid (48, BB), block 128.  hh<32: q head; 32..39: k head; 40..47: v head (no rotate).
__global__ void __launch_bounds__(128)
fused_reduce_rot_kernel(const float* __restrict__ rot, int rot_b_stride)
{
    const int hh = blockIdx.x, b = blockIdx.y, tid = threadIdx.x;
    int col;
    if (hh < 32)      col = hh * 128 + tid;
    else if (hh < 40) col = 4096 + (hh - 32) * 128 + tid;
    else              col = 5120 + (hh - 40) * 128 + tid;

    const float* p = g_P1 + (size_t)b * EQKV + col;
    float s = 0.f;
    #pragma unroll
    for (int sp = 0; sp < SPL; sp++)
        s += p[(size_t)sp * BB * EQKV];

    if (hh >= 40) {                      // v: plain reduce
        g_v[(size_t)b * 1024 + (hh - 40) * 128 + tid] = s;
        return;
    }

    __shared__ float xsr[DH];
    xsr[tid] = s;
    __syncthreads();
    const float* R = rot + (size_t)b * rot_b_stride;
    float a = 0.f;
    #pragma unroll 8
    for (int dd = 0; dd < DH; dd++) a += xsr[dd] * R[dd * DH + tid];

    if (hh < 32) g_q[(size_t)(b * HH + hh) * DH + tid] = a;
    else         g_k[(size_t)(b * HKV + (hh - 32)) * DH + tid] = a;
}

// ---------------- reduce wo partials ----------------
__global__ void reduce_o_kernel(float* __restrict__ out)
{
    int idx = blockIdx.x * 256 + threadIdx.x;
    if (idx >= BB * DD) return;
    int b = idx >> 12, col = idx & 4095;
    float s = 0.f;
    #pragma unroll
    for (int sp = 0; sp < SPL; sp++)
        s += g_P2[((size_t)sp * BB + b) * DD + col];
    out[b * DD + col] = s;
}

// ---------------- flash decode: direct-LDG, 256 tokens/CTA, single-pass softmax ----------------
// grid (NSPLIT, HKV, BB), block 256 (8 warps x 32 tokens).  (R7-measured config)
__global__ void __launch_bounds__(256, 3)
attn_kernel(const float* __restrict__ kc, const float* __restrict__ vc,
            const int* __restrict__ sp_ptr)
{
    __shared__ float s_q  [GG * DH];
    __shared__ float s_sc [TCH * GG];
    __shared__ float s_wm [8 * GG];
    __shared__ float s_sl [8 * GG];
    __shared__ float s_MM [GG];
    __shared__ float s_out[8 * GG * DH];

    const int chunk = blockIdx.x, kvh = blockIdx.y, b = blockIdx.z;
    const int sp = *sp_ptr;
    const int t0 = chunk * TCH;
    if (t0 > sp) return;

    const int tid = threadIdx.x;
    const int wid = tid >> 5, lane = tid & 31;
    const int bkv = b * HKV + kvh;

    const float* kbase = kc + (size_t)bkv * TT * DH;
    const float* vbase = vc + (size_t)bkv * TT * DH;
    const float* gk = g_k + (size_t)bkv * DH;
    const float* gv = g_v + (size_t)bkv * DH;

    if (tid < 128) {
        int g = tid >> 5, c = tid & 31;
        const float sc = 0.08838834764831845f;   // 1/sqrt(128)
        float4 qv = *(const float4*)(g_q + (size_t)(b * HH + kvh * GG + g) * DH + c * 4);
        ((float4*)s_q)[g * 32 + c] = make_float4(qv.x * sc, qv.y * sc, qv.z * sc, qv.w * sc);
    }
    __syncthreads();

    const int tokg = lane >> 4, dg = lane & 15;
    const int jb = wid * 32;

    float4 qr0[GG], qr1[GG];
    #pragma unroll
    for (int g = 0; g < GG; g++) {
        qr0[g] = *(const float4*)(s_q + g * DH + dg * 4);
        qr1[g] = *(const float4*)(s_q + g * DH + dg * 4 + 64);
    }

    float wm0 = -1e30f, wm1 = -1e30f, wm2 = -1e30f, wm3 = -1e30f;
    float4 ka, kb;
    {
        int t = t0 + jb + tokg;
        const float* kp = (t == sp) ? gk : (kbase + (size_t)t * DH);
        ka = *(const float4*)(kp + dg * 4);
        kb = *(const float4*)(kp + dg * 4 + 64);
    }
    #pragma unroll
    for (int it = 0; it < 16; it++) {
        int jl = jb + it * 2 + tokg;
        int t = t0 + jl;
        float4 ca = ka, cb = kb;
        if (it < 15) {
            int tn = t0 + jb + (it + 1) * 2 + tokg;
            const float* kp = (tn == sp) ? gk : (kbase + (size_t)tn * DH);
            ka = *(const float4*)(kp + dg * 4);
            kb = *(const float4*)(kp + dg * 4 + 64);
        }
        float s0 = ca.x*qr0[0].x + ca.y*qr0[0].y + ca.z*qr0[0].z + ca.w*qr0[0].w
                 + cb.x*qr1[0].x + cb.y*qr1[0].y + cb.z*qr1[0].z + cb.w*qr1[0].w;
        float s1 = ca.x*qr0[1].x + ca.y*qr0[1].y + ca.z*qr0[1].z + ca.w*qr0[1].w
                 + cb.x*qr1[1].x + cb.y*qr1[1].y + cb.z*qr1[1].z + cb.w*qr1[1].w;
        float s2 = ca.x*qr0[2].x + ca.y*qr0[2].y + ca.z*qr0[2].z + ca.w*qr0[2].w
                 + cb.x*qr1[2].x + cb.y*qr1[2].y + cb.z*qr1[2].z + cb.w*qr1[2].w;
        float s3 = ca.x*qr0[3].x + ca.y*qr0[3].y + ca.z*qr0[3].z + ca.w*qr0[3].w
                 + cb.x*qr1[3].x + cb.y*qr1[3].y + cb.z*qr1[3].z + cb.w*qr1[3].w;
        #pragma unroll
        for (int off = 1; off <= 8; off <<= 1) {
            s0 += __shfl_xor_sync(0xffffffffu, s0, off);
            s1 += __shfl_xor_sync(0xffffffffu, s1, off);
            s2 += __shfl_xor_sync(0xffffffffu, s2, off);
            s3 += __shfl_xor_sync(0xffffffffu, s3, off);
        }
        if (t > sp) { s0 = s1 = s2 = s3 = -1e30f; }
        if (dg == 0)
            ((float4*)s_sc)[jl] = make_float4(s0, s1, s2, s3);
        wm0 = fmaxf(wm0, s0); wm1 = fmaxf(wm1, s1);
        wm2 = fmaxf(wm2, s2); wm3 = fmaxf(wm3, s3);
    }
    wm0 = fmaxf(wm0, __shfl_xor_sync(0xffffffffu, wm0, 16));
    wm1 = fmaxf(wm1, __shfl_xor_sync(0xffffffffu, wm1, 16));
    wm2 = fmaxf(wm2, __shfl_xor_sync(0xffffffffu, wm2, 16));
    wm3 = fmaxf(wm3, __shfl_xor_sync(0xffffffffu, wm3, 16));
    if (lane == 0) {
        s_wm[wid * 4 + 0] = wm0; s_wm[wid * 4 + 1] = wm1;
        s_wm[wid * 4 + 2] = wm2; s_wm[wid * 4 + 3] = wm3;
    }
    __syncthreads();

    if (tid < 4) {
        float m = s_wm[tid];
        #pragma unroll
        for (int w = 1; w < 8; w++) m = fmaxf(m, s_wm[w * 4 + tid]);
        s_MM[tid] = m;
    }
    __syncthreads();

    // exp + per-warp sums (thread = token)
    {
        float4 sv = ((float4*)s_sc)[tid];
        float p0 = __expf(sv.x - s_MM[0]);
        float p1 = __expf(sv.y - s_MM[1]);
        float p2 = __expf(sv.z - s_MM[2]);
        float p3 = __expf(sv.w - s_MM[3]);
        ((float4*)s_sc)[tid] = make_float4(p0, p1, p2, p3);
        #pragma unroll
        for (int off = 1; off <= 16; off <<= 1) {
            p0 += __shfl_xor_sync(0xffffffffu, p0, off);
            p1 += __shfl_xor_sync(0xffffffffu, p1, off);
            p2 += __shfl_xor_sync(0xffffffffu, p2, off);
            p3 += __shfl_xor_sync(0xffffffffu, p3, off);
        }
        if (lane == 0) {
            s_sl[wid * 4 + 0] = p0; s_sl[wid * 4 + 1] = p1;
            s_sl[wid * 4 + 2] = p2; s_sl[wid * 4 + 3] = p3;
        }
    }
    __syncthreads();

    if (tid < 4) {
        float L = 0.f;
        #pragma unroll
        for (int w = 0; w < 8; w++) L += s_sl[w * 4 + tid];
        size_t mlb = (((size_t)bkv * NSPLIT + chunk) * GG + tid) * 2;
        g_pml[mlb] = s_MM[tid];
        g_pml[mlb + 1] = L;
    }

    // value phase
    float4 a0 = {0,0,0,0}, a1 = {0,0,0,0}, a2 = {0,0,0,0}, a3 = {0,0,0,0};
    #pragma unroll
    for (int jo = 0; jo < 32; jo += 4) {
        float4 vv[4], p4[4];
        #pragma unroll
        for (int u = 0; u < 4; u++) {
            int t = t0 + jb + jo + u;
            const float* vp = (t == sp) ? gv : (vbase + (size_t)t * DH);
            vv[u] = *(const float4*)(vp + lane * 4);
            p4[u] = ((float4*)s_sc)[jb + jo + u];
        }
        #pragma unroll
        for (int u = 0; u < 4; u++) {
            a0.x += p4[u].x*vv[u].x; a0.y += p4[u].x*vv[u].y; a0.z += p4[u].x*vv[u].z; a0.w += p4[u].x*vv[u].w;
            a1.x += p4[u].y*vv[u].x; a1.y += p4[u].y*vv[u].y; a1.z += p4[u].y*vv[u].z; a1.w += p4[u].y*vv[u].w;
            a2.x += p4[u].z*vv[u].x; a2.y += p4[u].z*vv[u].y; a2.z += p4[u].z*vv[u].z; a2.w += p4[u].z*vv[u].w;
            a3.x += p4[u].w*vv[u].x; a3.y += p4[u].w*vv[u].y; a3.z += p4[u].w*vv[u].z; a3.w += p4[u].w*vv[u].w;
        }
    }
    {
        float* ob = s_out + wid * (GG * DH);
        *(float4*)(ob + 0 * DH + lane * 4) = a0;
        *(float4*)(ob + 1 * DH + lane * 4) = a1;
        *(float4*)(ob + 2 * DH + lane * 4) = a2;
        *(float4*)(ob + 3 * DH + lane * 4) = a3;
    }
    __syncthreads();

    size_t obase = (((size_t)bkv * NSPLIT + chunk) * GG) * DH;
    #pragma unroll
    for (int r = tid; r < GG * DH; r += 256) {
        float s = 0.f;
        #pragma unroll
        for (int w = 0; w < 8; w++) s += s_out[w * (GG * DH) + r];
        g_pacc[obase + r] = s;
    }
}

// ---------------- combine split-KV partials + pack bf16 hi/lo for wo MMA ----------------
__global__ void combine_kernel(const int* __restrict__ sp_ptr)
{
    const int h = blockIdx.x, b = blockIdx.y, d = threadIdx.x;
    const int sp = *sp_ptr;
    const int nact = sp / TCH + 1;
    const int kvh = h >> 2, g = h & 3;
    const int bkv = b * HKV + kvh;

    float M = -1e30f;
    for (int c = 0; c < nact; c++)
        M = fmaxf(M, g_pml[(((size_t)bkv * NSPLIT + c) * GG + g) * 2]);

    float L = 0.f, acc = 0.f;
    for (int c = 0; c < nact; c++) {
        size_t mlb = (((size_t)bkv * NSPLIT + c) * GG + g) * 2;
        float f = __expf(g_pml[mlb] - M);
        L += g_pml[mlb + 1] * f;
        acc += g_pacc[(((size_t)bkv * NSPLIT + c) * GG + g) * DH + d] * f;
    }
    float res = acc / L;

    // pack pairs (even d holds elems 2i=res, 2i+1=neighbor) into bf16 hi/lo
    float other = __shfl_down_sync(0xffffffffu, res, 1);
    if ((d & 1) == 0) {
        uint32_t u0 = __float_as_uint(res), u1 = __float_as_uint(other);
        uint32_t hiv = __byte_perm(u0, u1, 0x7632);
        float l0 = res   - __uint_as_float(u0 & 0xFFFF0000u);
        float l1 = other - __uint_as_float(u1 & 0xFFFF0000u);
        uint32_t lov = cvt_bf16x2(l1, l0);
        size_t p = (size_t)(b * HH + h) * (DH / 2) + (d >> 1);
        g_ahi[p] = hiv;
        g_alo[p] = lov;
    }
}

// ---------------- launcher ----------------
extern "C" void kernel_launch(void* const* d_in, const int* in_sizes, int n_in,
                              void* d_out, int out_size)
{
    const float* x   = (const float*)d_in[0];
    const float* wq  = (const float*)d_in[1];
    const float* wk  = (const float*)d_in[2];
    const float* wv  = (const float*)d_in[3];
    const float* wo  = (const float*)d_in[4];
    const float* rot = (const float*)d_in[5];
    // d_in[6] = attn_mask: not read (semantics derived from start_pos)
    const float* kc  = (const float*)d_in[7];
    const float* vc  = (const float*)d_in[8];
    const int*   sp  = (const int*)d_in[9];
    float* out = (float*)d_out;

    int rot_b_stride = (in_sizes[5] >= BB * DH * DH) ? DH * DH : 0;

    uint32_t *xhi_p, *xlo_p;
    cudaGetSymbolAddress((void**)&xhi_p, g_xhi);
    cudaGetSymbolAddress((void**)&xlo_p, g_xlo);

    const int NPAIRS = BB * DD / 2;   // 65536

    conv_hilo_kernel<<<(NPAIRS + 255) / 256, 256>>>(x, xhi_p, xlo_p, NPAIRS);
    proj_qkv_mma<<<dim3(EQKV / 128, SPL), 128>>>(wq, wk, wv);
    fused_reduce_rot_kernel<<<dim3(48, BB), 128>>>(rot, rot_b_stride);
    attn_kernel<<<dim3(NSPLIT, HKV, BB), 256>>>(kc, vc, sp);
    combine_kernel<<<dim3(HH, BB), DH>>>(sp);
    proj_o_mma<<<dim3(DD / 128, SPL), 128>>>(wo);
    reduce_o_kernel<<<(BB * DD + 255) / 256, 256>>>(out);
}

// round 13
// speedup vs baseline: 1.8999x; 1.1989x over previous
#include <cuda_runtime.h>
#include <cuda_bf16.h>
#include <cstdint>

// Problem constants
#define BB   32      // batch
#define DD   4096    // model dim
#define HH   32      // q heads
#define HKV  8       // kv heads
#define GG   4       // q heads per kv head
#define DH   128     // head dim
#define TT   4096    // cache length
#define EQKV 6144    // 4096 + 1024 + 1024
#define SPL  16      // K splits for mma projections
#define KSP  256     // DD / SPL
#define ASTR 132     // padded smem stride (uint32 words) for A tile

// attention split config
#define TCH    256   // tokens per CTA
#define NSPLIT 16    // TT / TCH

// ---------------- scratch (device globals; no runtime allocation) ----------------
__device__ float g_v [BB * HKV * DH];
__device__ float g_q [BB * HH * DH];
__device__ float g_k [BB * HKV * DH];
__device__ uint32_t g_xhi[BB * DD / 2];   // packed bf16x2 hi of x
__device__ uint32_t g_xlo[BB * DD / 2];   // packed bf16x2 lo of x
__device__ uint32_t g_ahi[BB * DD / 2];   // packed bf16x2 hi of attn out
__device__ uint32_t g_alo[BB * DD / 2];
__device__ float g_P1[SPL * BB * EQKV];               // qkv partials
__device__ float g_P2[SPL * BB * DD];                 // wo partials
__device__ float g_pacc[BB * HKV * NSPLIT * GG * DH]; // flash partial acc
__device__ float g_pml [BB * HKV * NSPLIT * GG * 2];  // flash partial (m,l)

// ---------------- bf16 mma helper ----------------
__device__ __forceinline__ void mma_bf16(float* c, const uint32_t* a, uint32_t b0, uint32_t b1)
{
    asm volatile(
        "mma.sync.aligned.m16n8k16.row.col.f32.bf16.bf16.f32 "
        "{%0,%1,%2,%3}, {%4,%5,%6,%7}, {%8,%9}, {%0,%1,%2,%3};"
        : "+f"(c[0]), "+f"(c[1]), "+f"(c[2]), "+f"(c[3])
        : "r"(a[0]), "r"(a[1]), "r"(a[2]), "r"(a[3]), "r"(b0), "r"(b1));
}

__device__ __forceinline__ uint32_t cvt_bf16x2(float hi_elem, float lo_elem)
{
    uint32_t r;
    asm("cvt.rn.bf16x2.f32 %0, %1, %2;" : "=r"(r) : "f"(hi_elem), "f"(lo_elem));
    return r;
}

// ---------------- fp32 -> packed bf16 hi/lo conversion (x input) ----------------
__global__ void conv_hilo_kernel(const float* __restrict__ src,
                                 uint32_t* __restrict__ hi, uint32_t* __restrict__ lo,
                                 int npairs)
{
    int i = blockIdx.x * 256 + threadIdx.x;
    if (i >= npairs) return;
    float2 v = ((const float2*)src)[i];
    uint32_t u0 = __float_as_uint(v.x), u1 = __float_as_uint(v.y);
    hi[i] = __byte_perm(u0, u1, 0x7632);          // {bf16(v.y)|bf16(v.x)} truncated
    float l0 = v.x - __uint_as_float(u0 & 0xFFFF0000u);
    float l1 = v.y - __uint_as_float(u1 & 0xFFFF0000u);
    lo[i] = cvt_bf16x2(l1, l0);
}

// ---------------- tensor-core projection (bf16x3, A smem-staged) ----------------
// CTA: 128 threads = 4 warps; warp owns 32 cols; CTA N-tile 128; K-split blockIdx.y.
struct BFrag { float bf[4][4]; };

__device__ __forceinline__ void load_bfrag(
    BFrag& f, const float* __restrict__ w, int Ew, int wcol0, int k0, int tig)
{
    const float* wk0 = w + (size_t)(k0 + 2 * tig) * Ew + wcol0;
    #pragma unroll
    for (int nb = 0; nb < 4; nb++) {
        const float* wp = wk0 + nb * 8;
        f.bf[nb][0] = wp[0];
        f.bf[nb][1] = wp[Ew];
        f.bf[nb][2] = wp[(size_t)8 * Ew];
        f.bf[nb][3] = wp[(size_t)9 * Ew];
    }
}

__device__ __forceinline__ void mma_step(
    float acc[4][2][4], const BFrag& f,
    const uint32_t* __restrict__ s_ahi, const uint32_t* __restrict__ s_alo,
    int cword, int g, int tig)
{
    // A fragments from smem (bank-conflict-free: banks = 4g+tig)
    uint32_t ahi[2][4], alo[2][4];
    #pragma unroll
    for (int mt = 0; mt < 2; mt++) {
        int rb = (mt * 16 + g) * ASTR + cword + tig;
        ahi[mt][0] = s_ahi[rb];
        ahi[mt][1] = s_ahi[rb + 8 * ASTR];
        ahi[mt][2] = s_ahi[rb + 4];
        ahi[mt][3] = s_ahi[rb + 8 * ASTR + 4];
        alo[mt][0] = s_alo[rb];
        alo[mt][1] = s_alo[rb + 8 * ASTR];
        alo[mt][2] = s_alo[rb + 4];
        alo[mt][3] = s_alo[rb + 8 * ASTR + 4];
    }
    #pragma unroll
    for (int nb = 0; nb < 4; nb++) {
        uint32_t u0 = __float_as_uint(f.bf[nb][0]), u1 = __float_as_uint(f.bf[nb][1]);
        uint32_t u2 = __float_as_uint(f.bf[nb][2]), u3 = __float_as_uint(f.bf[nb][3]);
        uint32_t bhi0 = __byte_perm(u0, u1, 0x7632);
        uint32_t bhi1 = __byte_perm(u2, u3, 0x7632);
        float l0 = f.bf[nb][0] - __uint_as_float(u0 & 0xFFFF0000u);
        float l1 = f.bf[nb][1] - __uint_as_float(u1 & 0xFFFF0000u);
        float l2 = f.bf[nb][2] - __uint_as_float(u2 & 0xFFFF0000u);
        float l3 = f.bf[nb][3] - __uint_as_float(u3 & 0xFFFF0000u);
        uint32_t blo0 = cvt_bf16x2(l1, l0);
        uint32_t blo1 = cvt_bf16x2(l3, l2);
        #pragma unroll
        for (int mt = 0; mt < 2; mt++) {
            mma_bf16(acc[nb][mt], ahi[mt], bhi0, bhi1);   // hi*hi
            mma_bf16(acc[nb][mt], ahi[mt], blo0, blo1);   // hi*lo
            mma_bf16(acc[nb][mt], alo[mt], bhi0, bhi1);   // lo*hi
        }
    }
}

__device__ __forceinline__ void proj_mma_body(
    const uint32_t* __restrict__ xhi, const uint32_t* __restrict__ xlo,
    const float* __restrict__ w, int Ew, int le0, int gcol0,
    float* __restrict__ part, int partE)
{
    __shared__ uint32_t s_ahi[32 * ASTR];   // 16.9 KB
    __shared__ uint32_t s_alo[32 * ASTR];

    const int tid = threadIdx.x;
    const int wid = tid >> 5, lane = tid & 31;
    const int g = lane >> 2, tig = lane & 3;
    const int nwarp0 = wid * 32;
    const int k0base = blockIdx.y * KSP;
    const int wcol0 = le0 + nwarp0 + g;
    const int kw0 = k0base >> 1;            // word offset into packed arrays

    // ---- stage A tile (32 rows x 128 words), coalesced uint4 ----
    #pragma unroll
    for (int it = 0; it < 8; it++) {
        int idx = it * 128 + tid;           // 0..1023 = 32 rows x 32 word-quads
        int row = idx >> 5, w4 = (idx & 31) * 4;
        *(uint4*)&s_ahi[row * ASTR + w4] =
            *(const uint4*)&xhi[(size_t)row * (DD / 2) + kw0 + w4];
        *(uint4*)&s_alo[row * ASTR + w4] =
            *(const uint4*)&xlo[(size_t)row * (DD / 2) + kw0 + w4];
    }
    __syncthreads();

    float acc[4][2][4];
    #pragma unroll
    for (int nb = 0; nb < 4; nb++)
        #pragma unroll
        for (int mt = 0; mt < 2; mt++)
            #pragma unroll
            for (int r = 0; r < 4; r++) acc[nb][mt][r] = 0.f;

    const int NCH = KSP / 16;   // 16 chunks

    BFrag fA, fB;
    load_bfrag(fA, w, Ew, wcol0, k0base, tig);

    #pragma unroll 2
    for (int c = 0; c < NCH; c += 2) {
        load_bfrag(fB, w, Ew, wcol0, k0base + (c + 1) * 16, tig);
        mma_step(acc, fA, s_ahi, s_alo, c * 8, g, tig);
        if (c + 2 < NCH)
            load_bfrag(fA, w, Ew, wcol0, k0base + (c + 2) * 16, tig);
        mma_step(acc, fB, s_ahi, s_alo, (c + 1) * 8, g, tig);
    }

    // ---- writeback partials ----
    float* pb = part + (size_t)blockIdx.y * BB * partE;
    #pragma unroll
    for (int nb = 0; nb < 4; nb++) {
        int ecol = gcol0 + nwarp0 + nb * 8 + 2 * tig;
        #pragma unroll
        for (int mt = 0; mt < 2; mt++) {
            int brow = mt * 16 + g;
            *(float2*)(pb + (size_t)brow * partE + ecol) =
                make_float2(acc[nb][mt][0], acc[nb][mt][1]);
            *(float2*)(pb + (size_t)(brow + 8) * partE + ecol) =
                make_float2(acc[nb][mt][2], acc[nb][mt][3]);
        }
    }
}

__global__ void __launch_bounds__(128)
proj_qkv_mma(const float* __restrict__ wq, const float* __restrict__ wk,
             const float* __restrict__ wv)
{
    int e0 = blockIdx.x * 128;
    const float* w; int Ew, le0;
    if (e0 < 4096)      { w = wq; Ew = 4096; le0 = e0; }
    else if (e0 < 5120) { w = wk; Ew = 1024; le0 = e0 - 4096; }
    else                { w = wv; Ew = 1024; le0 = e0 - 5120; }
    proj_mma_body(g_xhi, g_xlo, w, Ew, le0, e0, g_P1, EQKV);
}

__global__ void __launch_bounds__(128)
proj_o_mma(const float* __restrict__ wo)
{
    int e0 = blockIdx.x * 128;
    proj_mma_body(g_ahi, g_alo, wo, DD, e0, e0, g_P2, DD);
}

// ---------------- fused split-reduce + RoPE ----------------
// grid (48, BB), block 128.  hh<32: q head; 32..39: k head; 40..47: v head (no rotate).
__global__ void __launch_bounds__(128)
fused_reduce_rot_kernel(const float* __restrict__ rot, int rot_b_stride)
{
    const int hh = blockIdx.x, b = blockIdx.y, tid = threadIdx.x;
    int col;
    if (hh < 32)      col = hh * 128 + tid;
    else if (hh < 40) col = 4096 + (hh - 32) * 128 + tid;
    else              col = 5120 + (hh - 40) * 128 + tid;

    const float* p = g_P1 + (size_t)b * EQKV + col;
    float s = 0.f;
    #pragma unroll
    for (int sp = 0; sp < SPL; sp++)
        s += p[(size_t)sp * BB * EQKV];

    if (hh >= 40) {                      // v: plain reduce
        g_v[(size_t)b * 1024 + (hh - 40) * 128 + tid] = s;
        return;
    }

    __shared__ float xsr[DH];
    xsr[tid] = s;
    __syncthreads();
    const float* R = rot + (size_t)b * rot_b_stride;
    float a = 0.f;
    #pragma unroll 8
    for (int dd = 0; dd < DH; dd++) a += xsr[dd] * R[dd * DH + tid];

    if (hh < 32) g_q[(size_t)(b * HH + hh) * DH + tid] = a;
    else         g_k[(size_t)(b * HKV + (hh - 32)) * DH + tid] = a;
}

// ---------------- reduce wo partials ----------------
__global__ void reduce_o_kernel(float* __restrict__ out)
{
    int idx = blockIdx.x * 256 + threadIdx.x;
    if (idx >= BB * DD) return;
    int b = idx >> 12, col = idx & 4095;
    float s = 0.f;
    #pragma unroll
    for (int sp = 0; sp < SPL; sp++)
        s += g_P2[((size_t)sp * BB + b) * DD + col];
    out[b * DD + col] = s;
}

// ---------------- flash decode: direct-LDG, 256 tokens/CTA, single-pass softmax ----------------
// grid (NSPLIT, HKV, BB), block 256 (8 warps x 32 tokens).  (R7/R12-measured config)
__global__ void __launch_bounds__(256, 3)
attn_kernel(const float* __restrict__ kc, const float* __restrict__ vc,
            const int* __restrict__ sp_ptr)
{
    __shared__ float s_q  [GG * DH];
    __shared__ float s_sc [TCH * GG];
    __shared__ float s_wm [8 * GG];
    __shared__ float s_sl [8 * GG];
    __shared__ float s_MM [GG];
    __shared__ float s_out[8 * GG * DH];

    const int chunk = blockIdx.x, kvh = blockIdx.y, b = blockIdx.z;
    const int sp = *sp_ptr;
    const int t0 = chunk * TCH;
    if (t0 > sp) return;

    const int tid = threadIdx.x;
    const int wid = tid >> 5, lane = tid & 31;
    const int bkv = b * HKV + kvh;

    const float* kbase = kc + (size_t)bkv * TT * DH;
    const float* vbase = vc + (size_t)bkv * TT * DH;
    const float* gk = g_k + (size_t)bkv * DH;
    const float* gv = g_v + (size_t)bkv * DH;

    if (tid < 128) {
        int g = tid >> 5, c = tid & 31;
        const float sc = 0.08838834764831845f;   // 1/sqrt(128)
        float4 qv = *(const float4*)(g_q + (size_t)(b * HH + kvh * GG + g) * DH + c * 4);
        ((float4*)s_q)[g * 32 + c] = make_float4(qv.x * sc, qv.y * sc, qv.z * sc, qv.w * sc);
    }
    __syncthreads();

    const int tokg = lane >> 4, dg = lane & 15;
    const int jb = wid * 32;

    float4 qr0[GG], qr1[GG];
    #pragma unroll
    for (int g = 0; g < GG; g++) {
        qr0[g] = *(const float4*)(s_q + g * DH + dg * 4);
        qr1[g] = *(const float4*)(s_q + g * DH + dg * 4 + 64);
    }

    float wm0 = -1e30f, wm1 = -1e30f, wm2 = -1e30f, wm3 = -1e30f;
    float4 ka, kb;
    {
        int t = t0 + jb + tokg;
        const float* kp = (t == sp) ? gk : (kbase + (size_t)t * DH);
        ka = *(const float4*)(kp + dg * 4);
        kb = *(const float4*)(kp + dg * 4 + 64);
    }
    #pragma unroll
    for (int it = 0; it < 16; it++) {
        int jl = jb + it * 2 + tokg;
        int t = t0 + jl;
        float4 ca = ka, cb = kb;
        if (it < 15) {
            int tn = t0 + jb + (it + 1) * 2 + tokg;
            const float* kp = (tn == sp) ? gk : (kbase + (size_t)tn * DH);
            ka = *(const float4*)(kp + dg * 4);
            kb = *(const float4*)(kp + dg * 4 + 64);
        }
        float s0 = ca.x*qr0[0].x + ca.y*qr0[0].y + ca.z*qr0[0].z + ca.w*qr0[0].w
                 + cb.x*qr1[0].x + cb.y*qr1[0].y + cb.z*qr1[0].z + cb.w*qr1[0].w;
        float s1 = ca.x*qr0[1].x + ca.y*qr0[1].y + ca.z*qr0[1].z + ca.w*qr0[1].w
                 + cb.x*qr1[1].x + cb.y*qr1[1].y + cb.z*qr1[1].z + cb.w*qr1[1].w;
        float s2 = ca.x*qr0[2].x + ca.y*qr0[2].y + ca.z*qr0[2].z + ca.w*qr0[2].w
                 + cb.x*qr1[2].x + cb.y*qr1[2].y + cb.z*qr1[2].z + cb.w*qr1[2].w;
        float s3 = ca.x*qr0[3].x + ca.y*qr0[3].y + ca.z*qr0[3].z + ca.w*qr0[3].w
                 + cb.x*qr1[3].x + cb.y*qr1[3].y + cb.z*qr1[3].z + cb.w*qr1[3].w;
        #pragma unroll
        for (int off = 1; off <= 8; off <<= 1) {
            s0 += __shfl_xor_sync(0xffffffffu, s0, off);
            s1 += __shfl_xor_sync(0xffffffffu, s1, off);
            s2 += __shfl_xor_sync(0xffffffffu, s2, off);
            s3 += __shfl_xor_sync(0xffffffffu, s3, off);
        }
        if (t > sp) { s0 = s1 = s2 = s3 = -1e30f; }
        if (dg == 0)
            ((float4*)s_sc)[jl] = make_float4(s0, s1, s2, s3);
        wm0 = fmaxf(wm0, s0); wm1 = fmaxf(wm1, s1);
        wm2 = fmaxf(wm2, s2); wm3 = fmaxf(wm3, s3);
    }
    wm0 = fmaxf(wm0, __shfl_xor_sync(0xffffffffu, wm0, 16));
    wm1 = fmaxf(wm1, __shfl_xor_sync(0xffffffffu, wm1, 16));
    wm2 = fmaxf(wm2, __shfl_xor_sync(0xffffffffu, wm2, 16));
    wm3 = fmaxf(wm3, __shfl_xor_sync(0xffffffffu, wm3, 16));
    if (lane == 0) {
        s_wm[wid * 4 + 0] = wm0; s_wm[wid * 4 + 1] = wm1;
        s_wm[wid * 4 + 2] = wm2; s_wm[wid * 4 + 3] = wm3;
    }
    __syncthreads();

    if (tid < 4) {
        float m = s_wm[tid];
        #pragma unroll
        for (int w = 1; w < 8; w++) m = fmaxf(m, s_wm[w * 4 + tid]);
        s_MM[tid] = m;
    }
    __syncthreads();

    // exp + per-warp sums (thread = token)
    {
        float4 sv = ((float4*)s_sc)[tid];
        float p0 = __expf(sv.x - s_MM[0]);
        float p1 = __expf(sv.y - s_MM[1]);
        float p2 = __expf(sv.z - s_MM[2]);
        float p3 = __expf(sv.w - s_MM[3]);
        ((float4*)s_sc)[tid] = make_float4(p0, p1, p2, p3);
        #pragma unroll
        for (int off = 1; off <= 16; off <<= 1) {
            p0 += __shfl_xor_sync(0xffffffffu, p0, off);
            p1 += __shfl_xor_sync(0xffffffffu, p1, off);
            p2 += __shfl_xor_sync(0xffffffffu, p2, off);
            p3 += __shfl_xor_sync(0xffffffffu, p3, off);
        }
        if (lane == 0) {
            s_sl[wid * 4 + 0] = p0; s_sl[wid * 4 + 1] = p1;
            s_sl[wid * 4 + 2] = p2; s_sl[wid * 4 + 3] = p3;
        }
    }
    __syncthreads();

    if (tid < 4) {
        float L = 0.f;
        #pragma unroll
        for (int w = 0; w < 8; w++) L += s_sl[w * 4 + tid];
        size_t mlb = (((size_t)bkv * NSPLIT + chunk) * GG + tid) * 2;
        g_pml[mlb] = s_MM[tid];
        g_pml[mlb + 1] = L;
    }

    // value phase
    float4 a0 = {0,0,0,0}, a1 = {0,0,0,0}, a2 = {0,0,0,0}, a3 = {0,0,0,0};
    #pragma unroll
    for (int jo = 0; jo < 32; jo += 4) {
        float4 vv[4], p4[4];
        #pragma unroll
        for (int u = 0; u < 4; u++) {
            int t = t0 + jb + jo + u;
            const float* vp = (t == sp) ? gv : (vbase + (size_t)t * DH);
            vv[u] = *(const float4*)(vp + lane * 4);
            p4[u] = ((float4*)s_sc)[jb + jo + u];
        }
        #pragma unroll
        for (int u = 0; u < 4; u++) {
            a0.x += p4[u].x*vv[u].x; a0.y += p4[u].x*vv[u].y; a0.z += p4[u].x*vv[u].z; a0.w += p4[u].x*vv[u].w;
            a1.x += p4[u].y*vv[u].x; a1.y += p4[u].y*vv[u].y; a1.z += p4[u].y*vv[u].z; a1.w += p4[u].y*vv[u].w;
            a2.x += p4[u].z*vv[u].x; a2.y += p4[u].z*vv[u].y; a2.z += p4[u].z*vv[u].z; a2.w += p4[u].z*vv[u].w;
            a3.x += p4[u].w*vv[u].x; a3.y += p4[u].w*vv[u].y; a3.z += p4[u].w*vv[u].z; a3.w += p4[u].w*vv[u].w;
        }
    }
    {
        float* ob = s_out + wid * (GG * DH);
        *(float4*)(ob + 0 * DH + lane * 4) = a0;
        *(float4*)(ob + 1 * DH + lane * 4) = a1;
        *(float4*)(ob + 2 * DH + lane * 4) = a2;
        *(float4*)(ob + 3 * DH + lane * 4) = a3;
    }
    __syncthreads();

    size_t obase = (((size_t)bkv * NSPLIT + chunk) * GG) * DH;
    #pragma unroll
    for (int r = tid; r < GG * DH; r += 256) {
        float s = 0.f;
        #pragma unroll
        for (int w = 0; w < 8; w++) s += s_out[w * (GG * DH) + r];
        g_pacc[obase + r] = s;
    }
}

// ---------------- combine split-KV partials + pack bf16 hi/lo for wo MMA ----------------
__global__ void combine_kernel(const int* __restrict__ sp_ptr)
{
    const int h = blockIdx.x, b = blockIdx.y, d = threadIdx.x;
    const int sp = *sp_ptr;
    const int nact = sp / TCH + 1;
    const int kvh = h >> 2, g = h & 3;
    const int bkv = b * HKV + kvh;

    float M = -1e30f;
    for (int c = 0; c < nact; c++)
        M = fmaxf(M, g_pml[(((size_t)bkv * NSPLIT + c) * GG + g) * 2]);

    float L = 0.f, acc = 0.f;
    for (int c = 0; c < nact; c++) {
        size_t mlb = (((size_t)bkv * NSPLIT + c) * GG + g) * 2;
        float f = __expf(g_pml[mlb] - M);
        L += g_pml[mlb + 1] * f;
        acc += g_pacc[(((size_t)bkv * NSPLIT + c) * GG + g) * DH + d] * f;
    }
    float res = acc / L;

    // pack pairs into bf16 hi/lo for the wo MMA
    float other = __shfl_down_sync(0xffffffffu, res, 1);
    if ((d & 1) == 0) {
        uint32_t u0 = __float_as_uint(res), u1 = __float_as_uint(other);
        uint32_t hiv = __byte_perm(u0, u1, 0x7632);
        float l0 = res   - __uint_as_float(u0 & 0xFFFF0000u);
        float l1 = other - __uint_as_float(u1 & 0xFFFF0000u);
        uint32_t lov = cvt_bf16x2(l1, l0);
        size_t p = (size_t)(b * HH + h) * (DH / 2) + (d >> 1);
        g_ahi[p] = hiv;
        g_alo[p] = lov;
    }
}

// ---------------- launcher ----------------
extern "C" void kernel_launch(void* const* d_in, const int* in_sizes, int n_in,
                              void* d_out, int out_size)
{
    const float* x   = (const float*)d_in[0];
    const float* wq  = (const float*)d_in[1];
    const float* wk  = (const float*)d_in[2];
    const float* wv  = (const float*)d_in[3];
    const float* wo  = (const float*)d_in[4];
    const float* rot = (const float*)d_in[5];
    // d_in[6] = attn_mask: not read (semantics derived from start_pos)
    const float* kc  = (const float*)d_in[7];
    const float* vc  = (const float*)d_in[8];
    const int*   sp  = (const int*)d_in[9];
    float* out = (float*)d_out;

    int rot_b_stride = (in_sizes[5] >= BB * DH * DH) ? DH * DH : 0;

    uint32_t *xhi_p, *xlo_p;
    cudaGetSymbolAddress((void**)&xhi_p, g_xhi);
    cudaGetSymbolAddress((void**)&xlo_p, g_xlo);

    const int NPAIRS = BB * DD / 2;   // 65536

    conv_hilo_kernel<<<(NPAIRS + 255) / 256, 256>>>(x, xhi_p, xlo_p, NPAIRS);
    proj_qkv_mma<<<dim3(EQKV / 128, SPL), 128>>>(wq, wk, wv);
    fused_reduce_rot_kernel<<<dim3(48, BB), 128>>>(rot, rot_b_stride);
    attn_kernel<<<dim3(NSPLIT, HKV, BB), 256>>>(kc, vc, sp);
    combine_kernel<<<dim3(HH, BB), DH>>>(sp);
    proj_o_mma<<<dim3(DD / 128, SPL), 128>>>(wo);
    reduce_o_kernel<<<(BB * DD + 255) / 256, 256>>>(out);
}

// round 14
// speedup vs baseline: 2.0090x; 1.0574x over previous
#include <cuda_runtime.h>
#include <cuda_bf16.h>
#include <cstdint>

// Problem constants
#define BB   32      // batch
#define DD   4096    // model dim
#define HH   32      // q heads
#define HKV  8       // kv heads
#define GG   4       // q heads per kv head
#define DH   128     // head dim
#define TT   4096    // cache length
#define EQKV 6144    // 4096 + 1024 + 1024
#define SPL  16      // K splits for mma projections
#define KSP  256     // DD / SPL
#define ASTR 132     // padded smem stride (uint32 words) for A tile
#define BSTR 132     // padded smem stride (floats) for B chunk tile

// attention split config
#define TCH    256   // tokens per CTA
#define NSPLIT 16    // TT / TCH

// ---------------- scratch (device globals; no runtime allocation) ----------------
__device__ float g_v [BB * HKV * DH];
__device__ float g_q [BB * HH * DH];
__device__ float g_k [BB * HKV * DH];
__device__ uint32_t g_xhi[BB * DD / 2];   // packed bf16x2 hi of x
__device__ uint32_t g_xlo[BB * DD / 2];   // packed bf16x2 lo of x
__device__ uint32_t g_ahi[BB * DD / 2];   // packed bf16x2 hi of attn out
__device__ uint32_t g_alo[BB * DD / 2];
__device__ float g_P1[SPL * BB * EQKV];               // qkv partials
__device__ float g_P2[SPL * BB * DD];                 // wo partials
__device__ float g_pacc[BB * HKV * NSPLIT * GG * DH]; // flash partial acc
__device__ float g_pml [BB * HKV * NSPLIT * GG * 2];  // flash partial (m,l)

// ---------------- bf16 mma helper ----------------
__device__ __forceinline__ void mma_bf16(float* c, const uint32_t* a, uint32_t b0, uint32_t b1)
{
    asm volatile(
        "mma.sync.aligned.m16n8k16.row.col.f32.bf16.bf16.f32 "
        "{%0,%1,%2,%3}, {%4,%5,%6,%7}, {%8,%9}, {%0,%1,%2,%3};"
        : "+f"(c[0]), "+f"(c[1]), "+f"(c[2]), "+f"(c[3])
        : "r"(a[0]), "r"(a[1]), "r"(a[2]), "r"(a[3]), "r"(b0), "r"(b1));
}

__device__ __forceinline__ uint32_t cvt_bf16x2(float hi_elem, float lo_elem)
{
    uint32_t r;
    asm("cvt.rn.bf16x2.f32 %0, %1, %2;" : "=r"(r) : "f"(hi_elem), "f"(lo_elem));
    return r;
}

// ---------------- fp32 -> packed bf16 hi/lo conversion (x input) ----------------
__global__ void conv_hilo_kernel(const float* __restrict__ src,
                                 uint32_t* __restrict__ hi, uint32_t* __restrict__ lo,
                                 int npairs)
{
    int i = blockIdx.x * 256 + threadIdx.x;
    if (i >= npairs) return;
    float2 v = ((const float2*)src)[i];
    uint32_t u0 = __float_as_uint(v.x), u1 = __float_as_uint(v.y);
    hi[i] = __byte_perm(u0, u1, 0x7632);          // {bf16(v.y)|bf16(v.x)} truncated
    float l0 = v.x - __uint_as_float(u0 & 0xFFFF0000u);
    float l1 = v.y - __uint_as_float(u1 & 0xFFFF0000u);
    lo[i] = cvt_bf16x2(l1, l0);
}

// ---------------- tensor-core projection (bf16x3, A + B smem-staged) ----------------
// CTA: 128 threads = 4 warps; warp owns 32 cols; CTA N-tile 128; K-split blockIdx.y.
// B chunks (16 rows x 128 cols fp32) stream through a 2-buffer smem tile via
// register prefetch: LDG chunk c+2 -> regs while computing chunk c.

__device__ __forceinline__ void ldg_bchunk(
    float4 br[4], const float* __restrict__ w, int Ew, int le0, int k0, int tid)
{
    #pragma unroll
    for (int p = 0; p < 4; p++) {
        int idx = p * 128 + tid;
        int row = idx >> 5, quad = idx & 31;
        br[p] = __ldcs((const float4*)(w + (size_t)(k0 + row) * Ew + le0 + quad * 4));
    }
}

__device__ __forceinline__ void sts_bchunk(float* sb, const float4 br[4], int tid)
{
    #pragma unroll
    for (int p = 0; p < 4; p++) {
        int idx = p * 128 + tid;
        int row = idx >> 5, quad = idx & 31;
        *(float4*)&sb[row * BSTR + quad * 4] = br[p];
    }
}

__device__ __forceinline__ void mma_step(
    float acc[4][2][4],
    const uint32_t* __restrict__ s_ahi, const uint32_t* __restrict__ s_alo,
    const float* __restrict__ sb,
    int cword, int g, int tig, int nwarp0)
{
    // A fragments from smem (banks = 4g+tig, conflict-free)
    uint32_t ahi[2][4], alo[2][4];
    #pragma unroll
    for (int mt = 0; mt < 2; mt++) {
        int rb = (mt * 16 + g) * ASTR + cword + tig;
        ahi[mt][0] = s_ahi[rb];
        ahi[mt][1] = s_ahi[rb + 8 * ASTR];
        ahi[mt][2] = s_ahi[rb + 4];
        ahi[mt][3] = s_ahi[rb + 8 * ASTR + 4];
        alo[mt][0] = s_alo[rb];
        alo[mt][1] = s_alo[rb + 8 * ASTR];
        alo[mt][2] = s_alo[rb + 4];
        alo[mt][3] = s_alo[rb + 8 * ASTR + 4];
    }
    // B fragments from smem (banks = 8*tig+g, conflict-free)
    const float* bbase = sb + (2 * tig) * BSTR + nwarp0 + g;
    #pragma unroll
    for (int nb = 0; nb < 4; nb++) {
        float b00 = bbase[nb * 8];
        float b01 = bbase[nb * 8 + BSTR];
        float b10 = bbase[nb * 8 + 8 * BSTR];
        float b11 = bbase[nb * 8 + 9 * BSTR];
        uint32_t u0 = __float_as_uint(b00), u1 = __float_as_uint(b01);
        uint32_t u2 = __float_as_uint(b10), u3 = __float_as_uint(b11);
        uint32_t bhi0 = __byte_perm(u0, u1, 0x7632);
        uint32_t bhi1 = __byte_perm(u2, u3, 0x7632);
        float l0 = b00 - __uint_as_float(u0 & 0xFFFF0000u);
        float l1 = b01 - __uint_as_float(u1 & 0xFFFF0000u);
        float l2 = b10 - __uint_as_float(u2 & 0xFFFF0000u);
        float l3 = b11 - __uint_as_float(u3 & 0xFFFF0000u);
        uint32_t blo0 = cvt_bf16x2(l1, l0);
        uint32_t blo1 = cvt_bf16x2(l3, l2);
        #pragma unroll
        for (int mt = 0; mt < 2; mt++) {
            mma_bf16(acc[nb][mt], ahi[mt], bhi0, bhi1);   // hi*hi
            mma_bf16(acc[nb][mt], ahi[mt], blo0, blo1);   // hi*lo
            mma_bf16(acc[nb][mt], alo[mt], bhi0, bhi1);   // lo*hi
        }
    }
}

__device__ __forceinline__ void proj_mma_body(
    const uint32_t* __restrict__ xhi, const uint32_t* __restrict__ xlo,
    const float* __restrict__ w, int Ew, int le0, int gcol0,
    float* __restrict__ part, int partE)
{
    __shared__ uint32_t s_ahi[32 * ASTR];     // 16.9 KB
    __shared__ uint32_t s_alo[32 * ASTR];
    __shared__ float    s_b[2][16 * BSTR];    // 2 x 8.4 KB

    const int tid = threadIdx.x;
    const int wid = tid >> 5, lane = tid & 31;
    const int g = lane >> 2, tig = lane & 3;
    const int nwarp0 = wid * 32;
    const int k0base = blockIdx.y * KSP;
    const int kw0 = k0base >> 1;            // word offset into packed arrays

    // ---- stage A tile (32 rows x 128 words), coalesced uint4 ----
    #pragma unroll
    for (int it = 0; it < 8; it++) {
        int idx = it * 128 + tid;           // 0..1023 = 32 rows x 32 word-quads
        int row = idx >> 5, w4 = (idx & 31) * 4;
        *(uint4*)&s_ahi[row * ASTR + w4] =
            *(const uint4*)&xhi[(size_t)row * (DD / 2) + kw0 + w4];
        *(uint4*)&s_alo[row * ASTR + w4] =
            *(const uint4*)&xlo[(size_t)row * (DD / 2) + kw0 + w4];
    }

    float acc[4][2][4];
    #pragma unroll
    for (int nb = 0; nb < 4; nb++)
        #pragma unroll
        for (int mt = 0; mt < 2; mt++)
            #pragma unroll
            for (int r = 0; r < 4; r++) acc[nb][mt][r] = 0.f;

    const int NCH = KSP / 16;   // 16 chunks

    // prologue: chunk 0 staged, chunk 1 in regs
    float4 br[4];
    ldg_bchunk(br, w, Ew, le0, k0base, tid);
    sts_bchunk(s_b[0], br, tid);
    ldg_bchunk(br, w, Ew, le0, k0base + 16, tid);
    __syncthreads();    // A tile + s_b[0] visible

    for (int c = 0; c < NCH; c++) {
        if (c + 1 < NCH) sts_bchunk(s_b[(c + 1) & 1], br, tid);
        if (c + 2 < NCH) ldg_bchunk(br, w, Ew, le0, k0base + (c + 2) * 16, tid);
        __syncthreads();    // s_b[(c+1)&1] visible; s_b[c&1] already visible
        mma_step(acc, s_ahi, s_alo, s_b[c & 1], c * 8, g, tig, nwarp0);
        __syncthreads();    // all warps done reading s_b[c&1] before reuse
    }

    // ---- writeback partials ----
    float* pb = part + (size_t)blockIdx.y * BB * partE;
    #pragma unroll
    for (int nb = 0; nb < 4; nb++) {
        int ecol = gcol0 + nwarp0 + nb * 8 + 2 * tig;
        #pragma unroll
        for (int mt = 0; mt < 2; mt++) {
            int brow = mt * 16 + g;
            *(float2*)(pb + (size_t)brow * partE + ecol) =
                make_float2(acc[nb][mt][0], acc[nb][mt][1]);
            *(float2*)(pb + (size_t)(brow + 8) * partE + ecol) =
                make_float2(acc[nb][mt][2], acc[nb][mt][3]);
        }
    }
}

__global__ void __launch_bounds__(128)
proj_qkv_mma(const float* __restrict__ wq, const float* __restrict__ wk,
             const float* __restrict__ wv)
{
    int e0 = blockIdx.x * 128;
    const float* w; int Ew, le0;
    if (e0 < 4096)      { w = wq; Ew = 4096; le0 = e0; }
    else if (e0 < 5120) { w = wk; Ew = 1024; le0 = e0 - 4096; }
    else                { w = wv; Ew = 1024; le0 = e0 - 5120; }
    proj_mma_body(g_xhi, g_xlo, w, Ew, le0, e0, g_P1, EQKV);
}

__global__ void __launch_bounds__(128)
proj_o_mma(const float* __restrict__ wo)
{
    int e0 = blockIdx.x * 128;
    proj_mma_body(g_ahi, g_alo, wo, DD, e0, e0, g_P2, DD);
}

// ---------------- fused split-reduce + RoPE ----------------
// grid (48, BB), block 128.  hh<32: q head; 32..39: k head; 40..47: v head (no rotate).
__global__ void __launch_bounds__(128)
fused_reduce_rot_kernel(const float* __restrict__ rot, int rot_b_stride)
{
    const int hh = blockIdx.x, b = blockIdx.y, tid = threadIdx.x;
    int col;
    if (hh < 32)      col = hh * 128 + tid;
    else if (hh < 40) col = 4096 + (hh - 32) * 128 + tid;
    else              col = 5120 + (hh - 40) * 128 + tid;

    const float* p = g_P1 + (size_t)b * EQKV + col;
    float s = 0.f;
    #pragma unroll
    for (int sp = 0; sp < SPL; sp++)
        s += p[(size_t)sp * BB * EQKV];

    if (hh >= 40) {                      // v: plain reduce
        g_v[(size_t)b * 1024 + (hh - 40) * 128 + tid] = s;
        return;
    }

    __shared__ float xsr[DH];
    xsr[tid] = s;
    __syncthreads();
    const float* R = rot + (size_t)b * rot_b_stride;
    float a = 0.f;
    #pragma unroll 8
    for (int dd = 0; dd < DH; dd++) a += xsr[dd] * R[dd * DH + tid];

    if (hh < 32) g_q[(size_t)(b * HH + hh) * DH + tid] = a;
    else         g_k[(size_t)(b * HKV + (hh - 32)) * DH + tid] = a;
}

// ---------------- reduce wo partials ----------------
__global__ void reduce_o_kernel(float* __restrict__ out)
{
    int idx = blockIdx.x * 256 + threadIdx.x;
    if (idx >= BB * DD) return;
    int b = idx >> 12, col = idx & 4095;
    float s = 0.f;
    #pragma unroll
    for (int sp = 0; sp < SPL; sp++)
        s += g_P2[((size_t)sp * BB + b) * DD + col];
    out[b * DD + col] = s;
}

// ---------------- flash decode: direct-LDG, 256 tokens/CTA, single-pass softmax ----------------
// grid (NSPLIT, HKV, BB), block 256 (8 warps x 32 tokens).
__global__ void __launch_bounds__(256, 3)
attn_kernel(const float* __restrict__ kc, const float* __restrict__ vc,
            const int* __restrict__ sp_ptr)
{
    __shared__ float s_q  [GG * DH];
    __shared__ float s_sc [TCH * GG];
    __shared__ float s_wm [8 * GG];
    __shared__ float s_sl [8 * GG];
    __shared__ float s_MM [GG];
    __shared__ float s_out[8 * GG * DH];

    const int chunk = blockIdx.x, kvh = blockIdx.y, b = blockIdx.z;
    const int sp = *sp_ptr;
    const int t0 = chunk * TCH;
    if (t0 > sp) return;

    const int tid = threadIdx.x;
    const int wid = tid >> 5, lane = tid & 31;
    const int bkv = b * HKV + kvh;

    const float* kbase = kc + (size_t)bkv * TT * DH;
    const float* vbase = vc + (size_t)bkv * TT * DH;
    const float* gk = g_k + (size_t)bkv * DH;
    const float* gv = g_v + (size_t)bkv * DH;

    if (tid < 128) {
        int g = tid >> 5, c = tid & 31;
        const float sc = 0.08838834764831845f;   // 1/sqrt(128)
        float4 qv = *(const float4*)(g_q + (size_t)(b * HH + kvh * GG + g) * DH + c * 4);
        ((float4*)s_q)[g * 32 + c] = make_float4(qv.x * sc, qv.y * sc, qv.z * sc, qv.w * sc);
    }
    __syncthreads();

    const int tokg = lane >> 4, dg = lane & 15;
    const int jb = wid * 32;

    float4 qr0[GG], qr1[GG];
    #pragma unroll
    for (int g = 0; g < GG; g++) {
        qr0[g] = *(const float4*)(s_q + g * DH + dg * 4);
        qr1[g] = *(const float4*)(s_q + g * DH + dg * 4 + 64);
    }

    float wm0 = -1e30f, wm1 = -1e30f, wm2 = -1e30f, wm3 = -1e30f;
    float4 ka, kb;
    {
        int t = t0 + jb + tokg;
        const float* kp = (t == sp) ? gk : (kbase + (size_t)t * DH);
        ka = __ldcs((const float4*)(kp + dg * 4));
        kb = __ldcs((const float4*)(kp + dg * 4 + 64));
    }
    #pragma unroll
    for (int it = 0; it < 16; it++) {
        int jl = jb + it * 2 + tokg;
        int t = t0 + jl;
        float4 ca = ka, cb = kb;
        if (it < 15) {
            int tn = t0 + jb + (it + 1) * 2 + tokg;
            const float* kp = (tn == sp) ? gk : (kbase + (size_t)tn * DH);
            ka = __ldcs((const float4*)(kp + dg * 4));
            kb = __ldcs((const float4*)(kp + dg * 4 + 64));
        }
        float s0 = ca.x*qr0[0].x + ca.y*qr0[0].y + ca.z*qr0[0].z + ca.w*qr0[0].w
                 + cb.x*qr1[0].x + cb.y*qr1[0].y + cb.z*qr1[0].z + cb.w*qr1[0].w;
        float s1 = ca.x*qr0[1].x + ca.y*qr0[1].y + ca.z*qr0[1].z + ca.w*qr0[1].w
                 + cb.x*qr1[1].x + cb.y*qr1[1].y + cb.z*qr1[1].z + cb.w*qr1[1].w;
        float s2 = ca.x*qr0[2].x + ca.y*qr0[2].y + ca.z*qr0[2].z + ca.w*qr0[2].w
                 + cb.x*qr1[2].x + cb.y*qr1[2].y + cb.z*qr1[2].z + cb.w*qr1[2].w;
        float s3 = ca.x*qr0[3].x + ca.y*qr0[3].y + ca.z*qr0[3].z + ca.w*qr0[3].w
                 + cb.x*qr1[3].x + cb.y*qr1[3].y + cb.z*qr1[3].z + cb.w*qr1[3].w;
        #pragma unroll
        for (int off = 1; off <= 8; off <<= 1) {
            s0 += __shfl_xor_sync(0xffffffffu, s0, off);
            s1 += __shfl_xor_sync(0xffffffffu, s1, off);
            s2 += __shfl_xor_sync(0xffffffffu, s2, off);
            s3 += __shfl_xor_sync(0xffffffffu, s3, off);
        }
        if (t > sp) { s0 = s1 = s2 = s3 = -1e30f; }
        if (dg == 0)
            ((float4*)s_sc)[jl] = make_float4(s0, s1, s2, s3);
        wm0 = fmaxf(wm0, s0); wm1 = fmaxf(wm1, s1);
        wm2 = fmaxf(wm2, s2); wm3 = fmaxf(wm3, s3);
    }
    wm0 = fmaxf(wm0, __shfl_xor_sync(0xffffffffu, wm0, 16));
    wm1 = fmaxf(wm1, __shfl_xor_sync(0xffffffffu, wm1, 16));
    wm2 = fmaxf(wm2, __shfl_xor_sync(0xffffffffu, wm2, 16));
    wm3 = fmaxf(wm3, __shfl_xor_sync(0xffffffffu, wm3, 16));
    if (lane == 0) {
        s_wm[wid * 4 + 0] = wm0; s_wm[wid * 4 + 1] = wm1;
        s_wm[wid * 4 + 2] = wm2; s_wm[wid * 4 + 3] = wm3;
    }
    __syncthreads();

    if (tid < 4) {
        float m = s_wm[tid];
        #pragma unroll
        for (int w = 1; w < 8; w++) m = fmaxf(m, s_wm[w * 4 + tid]);
        s_MM[tid] = m;
    }
    __syncthreads();

    // exp + per-warp sums (thread = token)
    {
        float4 sv = ((float4*)s_sc)[tid];
        float p0 = __expf(sv.x - s_MM[0]);
        float p1 = __expf(sv.y - s_MM[1]);
        float p2 = __expf(sv.z - s_MM[2]);
        float p3 = __expf(sv.w - s_MM[3]);
        ((float4*)s_sc)[tid] = make_float4(p0, p1, p2, p3);
        #pragma unroll
        for (int off = 1; off <= 16; off <<= 1) {
            p0 += __shfl_xor_sync(0xffffffffu, p0, off);
            p1 += __shfl_xor_sync(0xffffffffu, p1, off);
            p2 += __shfl_xor_sync(0xffffffffu, p2, off);
            p3 += __shfl_xor_sync(0xffffffffu, p3, off);
        }
        if (lane == 0) {
            s_sl[wid * 4 + 0] = p0; s_sl[wid * 4 + 1] = p1;
            s_sl[wid * 4 + 2] = p2; s_sl[wid * 4 + 3] = p3;
        }
    }
    __syncthreads();

    if (tid < 4) {
        float L = 0.f;
        #pragma unroll
        for (int w = 0; w < 8; w++) L += s_sl[w * 4 + tid];
        size_t mlb = (((size_t)bkv * NSPLIT + chunk) * GG + tid) * 2;
        g_pml[mlb] = s_MM[tid];
        g_pml[mlb + 1] = L;
    }

    // value phase
    float4 a0 = {0,0,0,0}, a1 = {0,0,0,0}, a2 = {0,0,0,0}, a3 = {0,0,0,0};
    #pragma unroll
    for (int jo = 0; jo < 32; jo += 4) {
        float4 vv[4], p4[4];
        #pragma unroll
        for (int u = 0; u < 4; u++) {
            int t = t0 + jb + jo + u;
            const float* vp = (t == sp) ? gv : (vbase + (size_t)t * DH);
            vv[u] = __ldcs((const float4*)(vp + lane * 4));
            p4[u] = ((float4*)s_sc)[jb + jo + u];
        }
        #pragma unroll
        for (int u = 0; u < 4; u++) {
            a0.x += p4[u].x*vv[u].x; a0.y += p4[u].x*vv[u].y; a0.z += p4[u].x*vv[u].z; a0.w += p4[u].x*vv[u].w;
            a1.x += p4[u].y*vv[u].x; a1.y += p4[u].y*vv[u].y; a1.z += p4[u].y*vv[u].z; a1.w += p4[u].y*vv[u].w;
            a2.x += p4[u].z*vv[u].x; a2.y += p4[u].z*vv[u].y; a2.z += p4[u].z*vv[u].z; a2.w += p4[u].z*vv[u].w;
            a3.x += p4[u].w*vv[u].x; a3.y += p4[u].w*vv[u].y; a3.z += p4[u].w*vv[u].z; a3.w += p4[u].w*vv[u].w;
        }
    }
    {
        float* ob = s_out + wid * (GG * DH);
        *(float4*)(ob + 0 * DH + lane * 4) = a0;
        *(float4*)(ob + 1 * DH + lane * 4) = a1;
        *(float4*)(ob + 2 * DH + lane * 4) = a2;
        *(float4*)(ob + 3 * DH + lane * 4) = a3;
    }
    __syncthreads();

    size_t obase = (((size_t)bkv * NSPLIT + chunk) * GG) * DH;
    #pragma unroll
    for (int r = tid; r < GG * DH; r += 256) {
        float s = 0.f;
        #pragma unroll
        for (int w = 0; w < 8; w++) s += s_out[w * (GG * DH) + r];
        g_pacc[obase + r] = s;
    }
}

// ---------------- combine split-KV partials + pack bf16 hi/lo for wo MMA ----------------
__global__ void combine_kernel(const int* __restrict__ sp_ptr)
{
    const int h = blockIdx.x, b = blockIdx.y, d = threadIdx.x;
    const int sp = *sp_ptr;
    const int nact = sp / TCH + 1;
    const int kvh = h >> 2, g = h & 3;
    const int bkv = b * HKV + kvh;

    float M = -1e30f;
    for (int c = 0; c < nact; c++)
        M = fmaxf(M, g_pml[(((size_t)bkv * NSPLIT + c) * GG + g) * 2]);

    float L = 0.f, acc = 0.f;
    for (int c = 0; c < nact; c++) {
        size_t mlb = (((size_t)bkv * NSPLIT + c) * GG + g) * 2;
        float f = __expf(g_pml[mlb] - M);
        L += g_pml[mlb + 1] * f;
        acc += g_pacc[(((size_t)bkv * NSPLIT + c) * GG + g) * DH + d] * f;
    }
    float res = acc / L;

    // pack pairs into bf16 hi/lo for the wo MMA
    float other = __shfl_down_sync(0xffffffffu, res, 1);
    if ((d & 1) == 0) {
        uint32_t u0 = __float_as_uint(res), u1 = __float_as_uint(other);
        uint32_t hiv = __byte_perm(u0, u1, 0x7632);
        float l0 = res   - __uint_as_float(u0 & 0xFFFF0000u);
        float l1 = other - __uint_as_float(u1 & 0xFFFF0000u);
        uint32_t lov = cvt_bf16x2(l1, l0);
        size_t p = (size_t)(b * HH + h) * (DH / 2) + (d >> 1);
        g_ahi[p] = hiv;
        g_alo[p] = lov;
    }
}

// ---------------- launcher ----------------
extern "C" void kernel_launch(void* const* d_in, const int* in_sizes, int n_in,
                              void* d_out, int out_size)
{
    const float* x   = (const float*)d_in[0];
    const float* wq  = (const float*)d_in[1];
    const float* wk  = (const float*)d_in[2];
    const float* wv  = (const float*)d_in[3];
    const float* wo  = (const float*)d_in[4];
    const float* rot = (const float*)d_in[5];
    // d_in[6] = attn_mask: not read (semantics derived from start_pos)
    const float* kc  = (const float*)d_in[7];
    const float* vc  = (const float*)d_in[8];
    const int*   sp  = (const int*)d_in[9];
    float* out = (float*)d_out;

    int rot_b_stride = (in_sizes[5] >= BB * DH * DH) ? DH * DH : 0;

    uint32_t *xhi_p, *xlo_p;
    cudaGetSymbolAddress((void**)&xhi_p, g_xhi);
    cudaGetSymbolAddress((void**)&xlo_p, g_xlo);

    const int NPAIRS = BB * DD / 2;   // 65536

    conv_hilo_kernel<<<(NPAIRS + 255) / 256, 256>>>(x, xhi_p, xlo_p, NPAIRS);
    proj_qkv_mma<<<dim3(EQKV / 128, SPL), 128>>>(wq, wk, wv);
    fused_reduce_rot_kernel<<<dim3(48, BB), 128>>>(rot, rot_b_stride);
    attn_kernel<<<dim3(NSPLIT, HKV, BB), 256>>>(kc, vc, sp);
    combine_kernel<<<dim3(HH, BB), DH>>>(sp);
    proj_o_mma<<<dim3(DD / 128, SPL), 128>>>(wo);
    reduce_o_kernel<<<(BB * DD + 255) / 256, 256>>>(out);
}